// round 8
// baseline (speedup 1.0000x reference)
#include <cuda_runtime.h>
#include <cuda_bf16.h>
#include <cstdint>
#include <cstddef>

#define TT 2048
#define BB 16
#define DD 64
#define EE 512
#define NN (BB*TT)

// ---------------------------------------------------------------------------
// Global scratch
// ---------------------------------------------------------------------------
__device__ uint16_t g_qh[(size_t)NN * DD];       // q hi  (bf16 bits), row-major [N][64]
__device__ uint16_t g_ql[(size_t)NN * DD];       // q lo
__device__ uint16_t g_qTh[(size_t)NN * DD];      // q^T hi, [b][64][2048]
__device__ uint16_t g_qTl[(size_t)NN * DD];      // q^T lo
__device__ float    g_part[(size_t)NN * 16];     // per-(row, j-tile) exp partial sums
__device__ float    g_c[NN];                     // c = log(rowsumexp)

typedef unsigned long long ull;

// ---------------------------------------------------------------------------
// helpers
// ---------------------------------------------------------------------------
__device__ __forceinline__ uint32_t smem_u32(const void* p) {
    uint32_t a;
    asm("{ .reg .u64 t; cvta.to.shared.u64 t, %1; cvt.u32.u64 %0, t; }" : "=r"(a) : "l"(p));
    return a;
}
#define SWZ(o) ((o) ^ (((o) >> 3) & 0x70))

#define LDSM4(r0,r1,r2,r3,a) \
    asm volatile("ldmatrix.sync.aligned.m8n8.x4.shared.b16 {%0,%1,%2,%3}, [%4];" \
        : "=r"(r0),"=r"(r1),"=r"(r2),"=r"(r3) : "r"(a))

__device__ __forceinline__ void mma_bf16(float* d, const uint32_t* a,
                                         uint32_t b0, uint32_t b1) {
    asm volatile("mma.sync.aligned.m16n8k16.row.col.f32.bf16.bf16.f32 "
        "{%0,%1,%2,%3}, {%4,%5,%6,%7}, {%8,%9}, {%0,%1,%2,%3};"
        : "+f"(d[0]),"+f"(d[1]),"+f"(d[2]),"+f"(d[3])
        : "r"(a[0]),"r"(a[1]),"r"(a[2]),"r"(a[3]), "r"(b0),"r"(b1));
}

#define CPA16(dst, src) \
    asm volatile("cp.async.cg.shared.global [%0], [%1], 16;" :: "r"(dst), "l"(src) : "memory")
#define CP_COMMIT() asm volatile("cp.async.commit_group;" ::: "memory")
#define CP_WAIT1()  asm volatile("cp.async.wait_group 1;" ::: "memory")

// fp32 packed-FFMA helpers (K1)
__device__ __forceinline__ ull pk2(float x, float y) {
    ull r; asm("mov.b64 %0,{%1,%2};" : "=l"(r) : "f"(x), "f"(y)); return r;
}
__device__ __forceinline__ void fma2(ull &d, ull a, ull b) {
    asm("fma.rn.f32x2 %0,%1,%2,%0;" : "+l"(d) : "l"(a), "l"(b));
}
__device__ __forceinline__ void upk(ull v, float &x, float &y) {
    asm("mov.b64 {%0,%1},%2;" : "=f"(x), "=f"(y) : "l"(v));
}
__device__ __forceinline__ void bfsplit(float v, uint16_t &h, uint16_t &l) {
    __nv_bfloat16 hh = __float2bfloat16(v);
    float r = v - __bfloat162float(hh);
    __nv_bfloat16 ll = __float2bfloat16(r);
    h = __bfloat16_as_ushort(hh);
    l = __bfloat16_as_ushort(ll);
}

// ---------------------------------------------------------------------------
// K1: q = x @ Wq + bq  -> bf16 hi/lo row-major + transposed  (FFMA2 core)
// ---------------------------------------------------------------------------
__global__ __launch_bounds__(128) void k1_proj(
    const float* __restrict__ x, const float* __restrict__ Wq,
    const float* __restrict__ bq)
{
    extern __shared__ float sm[];
    float (*xsT)[132] = (float(*)[132])sm;
    float (*ws)[68]   = (float(*)[68])(sm + 64*132);
    float *bs = sm + 64*132 + 64*68;

    const int tid = threadIdx.x;
    const int r0 = blockIdx.x * 128;
    if (tid < 64) bs[tid] = bq[tid];

    const int tx = tid & 7, ty = tid >> 3;
    ull acc[8][4];
    #pragma unroll
    for (int r = 0; r < 8; r++)
        #pragma unroll
        for (int c = 0; c < 4; c++) acc[r][c] = 0ull;

    for (int kc = 0; kc < EE; kc += 64) {
        __syncthreads();
        #pragma unroll
        for (int idx = tid; idx < 1024; idx += 128) {
            int k = idx >> 4, qd = idx & 15;
            ((float4*)&ws[k][0])[qd] = ((const float4*)(Wq + (size_t)(kc + k) * DD))[qd];
        }
        const float* xr = x + (size_t)(r0 + tid) * EE + kc;
        #pragma unroll
        for (int u = 0; u < 16; u++) {
            float4 v = *(const float4*)(xr + u * 4);
            xsT[u*4+0][tid] = v.x; xsT[u*4+1][tid] = v.y;
            xsT[u*4+2][tid] = v.z; xsT[u*4+3][tid] = v.w;
        }
        __syncthreads();
        #pragma unroll 8
        for (int k = 0; k < 64; k++) {
            float4 a0 = *(const float4*)&xsT[k][ty*8];
            float4 a1 = *(const float4*)&xsT[k][ty*8+4];
            float4 b0 = *(const float4*)&ws[k][tx*4];
            float4 b1 = *(const float4*)&ws[k][32 + tx*4];
            ull bb0 = pk2(b0.x,b0.y), bb1 = pk2(b0.z,b0.w);
            ull bb2 = pk2(b1.x,b1.y), bb3 = pk2(b1.z,b1.w);
            float av[8] = {a0.x,a0.y,a0.z,a0.w,a1.x,a1.y,a1.z,a1.w};
            #pragma unroll
            for (int r = 0; r < 8; r++) {
                ull ar = pk2(av[r], av[r]);
                fma2(acc[r][0], ar, bb0); fma2(acc[r][1], ar, bb1);
                fma2(acc[r][2], ar, bb2); fma2(acc[r][3], ar, bb3);
            }
        }
    }
    __syncthreads();
    float (*qt)[132] = (float(*)[132])sm;   // [d][row_local]
    const int b = r0 >> 11;
    const int t0l = r0 & (TT - 1);

    #pragma unroll
    for (int r = 0; r < 8; r++) {
        float f[8];
        upk(acc[r][0], f[0], f[1]); upk(acc[r][1], f[2], f[3]);
        upk(acc[r][2], f[4], f[5]); upk(acc[r][3], f[6], f[7]);
        const int rl = ty*8 + r;
        const int row = r0 + rl;
        float v[8];
        #pragma unroll
        for (int c = 0; c < 4; c++) {
            v[c]   = f[c]   + bs[tx*4 + c];
            v[4+c] = f[4+c] + bs[32 + tx*4 + c];
        }
        #pragma unroll
        for (int c = 0; c < 4; c++) {
            qt[tx*4 + c][rl]      = v[c];
            qt[32 + tx*4 + c][rl] = v[4+c];
        }
        uint16_t h[8], l[8];
        #pragma unroll
        for (int c = 0; c < 8; c++) bfsplit(v[c], h[c], l[c]);
        uint2 uh0, ul0, uh1, ul1;
        uh0.x = (uint32_t)h[0] | ((uint32_t)h[1] << 16); uh0.y = (uint32_t)h[2] | ((uint32_t)h[3] << 16);
        uh1.x = (uint32_t)h[4] | ((uint32_t)h[5] << 16); uh1.y = (uint32_t)h[6] | ((uint32_t)h[7] << 16);
        ul0.x = (uint32_t)l[0] | ((uint32_t)l[1] << 16); ul0.y = (uint32_t)l[2] | ((uint32_t)l[3] << 16);
        ul1.x = (uint32_t)l[4] | ((uint32_t)l[5] << 16); ul1.y = (uint32_t)l[6] | ((uint32_t)l[7] << 16);
        *(uint2*)(g_qh + (size_t)row*DD + tx*4)      = uh0;
        *(uint2*)(g_qh + (size_t)row*DD + 32 + tx*4) = uh1;
        *(uint2*)(g_ql + (size_t)row*DD + tx*4)      = ul0;
        *(uint2*)(g_ql + (size_t)row*DD + 32 + tx*4) = ul1;
    }
    __syncthreads();
    for (int idx = tid; idx < 64*64; idx += 128) {
        int d = idx >> 6, tp = idx & 63;
        float v0 = qt[d][tp*2], v1 = qt[d][tp*2 + 1];
        uint16_t h0, l0, h1, l1;
        bfsplit(v0, h0, l0); bfsplit(v1, h1, l1);
        size_t off = ((size_t)b*DD + d)*TT + t0l + tp*2;
        *(uint32_t*)(g_qTh + off) = (uint32_t)h0 | ((uint32_t)h1 << 16);
        *(uint32_t*)(g_qTl + off) = (uint32_t)l0 | ((uint32_t)l1 << 16);
    }
}

// ---------------------------------------------------------------------------
// KA: stats only. S tile = (q_i . q_j^T)/8 via HMMA bf16 split; exp partial
// row & column sums -> g_part. NO S writes.  grid (136, 16), 256 threads.
// ---------------------------------------------------------------------------
#define KA_SMEM (65536 + 2048 + 1024)

__global__ __launch_bounds__(256) void ka_stats()
{
    extern __shared__ char smc[];
    float* rowpart = (float*)(smc + 65536);            // [4 wn][128 rows]
    float* colpart = (float*)(smc + 65536 + 2048);     // [2 wm][128 cols]
    const uint32_t sb = smem_u32(smc);
    const int tid = threadIdx.x, lane = tid & 31, w = tid >> 5;
    const int b = blockIdx.y;
    int jy = 0, rem = blockIdx.x;
    while (rem >= 16 - jy) { rem -= 16 - jy; jy++; }
    const int ix = jy + rem;
    const int i0 = ix * 128, j0 = jy * 128;

    #pragma unroll
    for (int it = 0; it < 16; it++) {
        int idx = it*256 + tid;
        int tile = idx >> 10;
        int r = (idx >> 3) & 127, ch = idx & 7;
        const uint16_t* src = (tile == 0 || tile == 2) ? g_qh : g_ql;
        int grow = (tile < 2) ? (i0 + r) : (j0 + r);
        int dst  = tile * 16384;
        uint4 v = *(const uint4*)(src + ((size_t)(b*TT + grow))*DD + ch*8);
        *(uint4*)(smc + dst + SWZ(r*128 + ch*16)) = v;
    }
    __syncthreads();

    const int wm = w >> 2, wn = w & 3;
    const int arow = lane & 15;
    const int acol = (lane & 16) >> 1;
    const int brow = (lane & 7) | ((lane & 16) >> 1);
    const int bcol = lane & 8;

    float d[16][4];
    #pragma unroll
    for (int t = 0; t < 16; t++)
        #pragma unroll
        for (int e = 0; e < 4; e++) d[t][e] = 0.f;

    #pragma unroll
    for (int split = 0; split < 3; split++) {
        const uint32_t Ab = sb + ((split == 2) ? 16384 : 0);
        const uint32_t Bb = sb + ((split == 1) ? 49152 : 32768);
        #pragma unroll
        for (int ks = 0; ks < 4; ks++) {
            uint32_t a[4][4];
            #pragma unroll
            for (int mt = 0; mt < 4; mt++)
                LDSM4(a[mt][0], a[mt][1], a[mt][2], a[mt][3],
                      Ab + SWZ((wm*64 + mt*16 + arow)*128 + (ks*16 + acol)*2));
            uint32_t bb[2][4];
            #pragma unroll
            for (int ng = 0; ng < 2; ng++)
                LDSM4(bb[ng][0], bb[ng][1], bb[ng][2], bb[ng][3],
                      Bb + SWZ((wn*32 + ng*16 + brow)*128 + (ks*16 + bcol)*2));
            #pragma unroll
            for (int mt = 0; mt < 4; mt++)
                #pragma unroll
                for (int nt = 0; nt < 4; nt++)
                    mma_bf16(d[mt*4+nt], a[mt],
                             bb[nt>>1][(nt&1)*2], bb[nt>>1][(nt&1)*2+1]);
        }
    }

    const int r_i = lane >> 2;
    const bool diag = (ix == jy);

    float rp[4][2], cp[4][2];
    #pragma unroll
    for (int t = 0; t < 4; t++) { rp[t][0]=rp[t][1]=0.f; cp[t][0]=cp[t][1]=0.f; }

    #pragma unroll
    for (int mt = 0; mt < 4; mt++) {
        #pragma unroll
        for (int nt = 0; nt < 4; nt++) {
            float e0 = __expf(d[mt*4+nt][0]*0.125f);
            float e1 = __expf(d[mt*4+nt][1]*0.125f);
            float e2 = __expf(d[mt*4+nt][2]*0.125f);
            float e3 = __expf(d[mt*4+nt][3]*0.125f);
            rp[mt][0] += e0 + e1;  rp[mt][1] += e2 + e3;
            cp[nt][0] += e0 + e2;  cp[nt][1] += e1 + e3;
        }
    }
    #pragma unroll
    for (int mt = 0; mt < 4; mt++) {
        float r0 = rp[mt][0], r1 = rp[mt][1];
        r0 += __shfl_xor_sync(0xffffffffu, r0, 1); r0 += __shfl_xor_sync(0xffffffffu, r0, 2);
        r1 += __shfl_xor_sync(0xffffffffu, r1, 1); r1 += __shfl_xor_sync(0xffffffffu, r1, 2);
        if ((lane & 3) == 0) {
            int rl = wm*64 + mt*16 + r_i;
            rowpart[wn*128 + rl]     = r0;
            rowpart[wn*128 + rl + 8] = r1;
        }
    }
    #pragma unroll
    for (int nt = 0; nt < 4; nt++) {
        float c0 = cp[nt][0], c1 = cp[nt][1];
        c0 += __shfl_xor_sync(0xffffffffu, c0, 4); c0 += __shfl_xor_sync(0xffffffffu, c0, 8);
        c0 += __shfl_xor_sync(0xffffffffu, c0, 16);
        c1 += __shfl_xor_sync(0xffffffffu, c1, 4); c1 += __shfl_xor_sync(0xffffffffu, c1, 8);
        c1 += __shfl_xor_sync(0xffffffffu, c1, 16);
        if (lane < 4) {
            int cl = wn*32 + nt*8 + lane*2;
            colpart[wm*128 + cl]     = c0;
            colpart[wm*128 + cl + 1] = c1;
        }
    }
    __syncthreads();

    if (tid < 128) {
        float rs = rowpart[tid] + rowpart[128+tid] + rowpart[256+tid] + rowpart[384+tid];
        g_part[((size_t)(b*TT + i0 + tid))*16 + jy] = rs;
        if (!diag) {
            float cs = colpart[tid] + colpart[128+tid];
            g_part[((size_t)(b*TT + j0 + tid))*16 + ix] = cs;
        }
    }
}

// ---------------------------------------------------------------------------
// K3': c[n] = log( sum of 16 partials )
// ---------------------------------------------------------------------------
__global__ __launch_bounds__(256) void k3_logz()
{
    const int n = blockIdx.x * 256 + threadIdx.x;
    const float* p = g_part + (size_t)n * 16;
    float4 a = *(const float4*)(p);
    float4 b = *(const float4*)(p + 4);
    float4 c = *(const float4*)(p + 8);
    float4 e = *(const float4*)(p + 12);
    float s = a.x + a.y + a.z + a.w;
    s += b.x + b.y + b.z + b.w;
    s += c.x + c.y + c.z + c.w;
    s += e.x + e.y + e.z + e.w;
    g_c[n] = logf(s);
}

// ---------------------------------------------------------------------------
// KB: fused out = P.q, S recomputed, P register-resident.
// Register-dieted for 2 CTAs/SM: q_i frags reloaded from resident smem tile,
// j-chunk processed in two 32-wide halves.
// grid (16 i-tiles of 128, 16 b), 256 threads (8 warps, each m16).
// ---------------------------------------------------------------------------
#define KB_STRIDE 33024
#define QJH(buf) ((buf)*KB_STRIDE)
#define QJL(buf) ((buf)*KB_STRIDE + 8192)
#define QTH(buf) ((buf)*KB_STRIDE + 16384)
#define QTL(buf) ((buf)*KB_STRIDE + 24576)
#define CBUF(buf) ((buf)*KB_STRIDE + 32768)
#define QI_H (2*KB_STRIDE)
#define QI_L (2*KB_STRIDE + 16384)
#define KB_SMEM (2*KB_STRIDE + 32768)

__global__ __launch_bounds__(256, 2) void kb_fused(float* __restrict__ out)
{
    extern __shared__ char smc[];
    const uint32_t sb = smem_u32(smc);
    const int tid = threadIdx.x, lane = tid & 31, w = tid >> 5;
    const int i0 = blockIdx.x * 128, b = blockIdx.y;

    const uint16_t* qh  = g_qh  + (size_t)b * TT * DD;
    const uint16_t* ql  = g_ql  + (size_t)b * TT * DD;
    const uint16_t* qTh = g_qTh + (size_t)b * DD * TT;
    const uint16_t* qTl = g_qTl + (size_t)b * DD * TT;
    const float*    cb  = g_c + b * TT;

    // --- stage q_i [128][64] hi/lo into resident smem tiles ---
    #pragma unroll
    for (int it = 0; it < 4; it++) {
        int idx = it*256 + tid;           // 1024: 128 rows x 8 segs
        int r = idx >> 3, seg = idx & 7;
        *(uint4*)(smc + QI_H + SWZ(r*128 + seg*16)) =
            *(const uint4*)(qh + (size_t)(i0 + r)*DD + seg*8);
        *(uint4*)(smc + QI_L + SWZ(r*128 + seg*16)) =
            *(const uint4*)(ql + (size_t)(i0 + r)*DD + seg*8);
    }

    auto prefetch = [&](int c, int buf) {
        const int j0c = c * 64;
        #pragma unroll
        for (int k2 = 0; k2 < 2; k2++) {
            int idx = k2*256 + tid;       // 512: 64 rows x 8 segs
            int r = idx >> 3, seg = idx & 7;
            CPA16(sb + QJH(buf) + SWZ(r*128 + seg*16),
                  (const void*)(qh + (size_t)(j0c + r)*DD + seg*8));
            CPA16(sb + QJL(buf) + SWZ(r*128 + seg*16),
                  (const void*)(ql + (size_t)(j0c + r)*DD + seg*8));
            CPA16(sb + QTH(buf) + SWZ(r*128 + seg*16),
                  (const void*)(qTh + (size_t)r*TT + j0c + seg*8));
            CPA16(sb + QTL(buf) + SWZ(r*128 + seg*16),
                  (const void*)(qTl + (size_t)r*TT + j0c + seg*8));
        }
        if (tid < 16)
            CPA16(sb + CBUF(buf) + tid*16, (const void*)(cb + j0c + tid*4));
    };

    prefetch(0, 0); CP_COMMIT();
    prefetch(1, 1); CP_COMMIT();
    __syncthreads();   // q_i staging visible to all warps

    const int arow = lane & 15;
    const int acol = (lane & 16) >> 1;
    const int brow = (lane & 7) | ((lane & 16) >> 1);
    const int bcol = lane & 8;

    float o[8][4];
    #pragma unroll
    for (int t = 0; t < 8; t++)
        #pragma unroll
        for (int e = 0; e < 4; e++) o[t][e] = 0.f;

    for (int c = 0; c < 32; c++) {
        const int buf = c & 1;
        CP_WAIT1();
        __syncthreads();

        #pragma unroll
        for (int half = 0; half < 2; half++) {
            // ---- MMA1: s = q_i . q_j^T for 32 j (3-split bf16) ----
            float s[4][4];
            #pragma unroll
            for (int t = 0; t < 4; t++)
                #pragma unroll
                for (int e = 0; e < 4; e++) s[t][e] = 0.f;

            #pragma unroll
            for (int split = 0; split < 3; split++) {
                const uint32_t Asrc = sb + ((split == 2) ? QI_L : QI_H);
                const uint32_t Bb = sb + ((split == 1) ? QJL(buf) : QJH(buf));
                #pragma unroll
                for (int ks = 0; ks < 4; ks++) {
                    uint32_t a[4];
                    LDSM4(a[0], a[1], a[2], a[3],
                          Asrc + SWZ((w*16 + arow)*128 + (ks*16 + acol)*2));
                    uint32_t bb[2][4];
                    #pragma unroll
                    for (int ng = 0; ng < 2; ng++)
                        LDSM4(bb[ng][0], bb[ng][1], bb[ng][2], bb[ng][3],
                              Bb + SWZ((half*32 + ng*16 + brow)*128 + (ks*16 + bcol)*2));
                    #pragma unroll
                    for (int nt = 0; nt < 4; nt++)
                        mma_bf16(s[nt], a, bb[nt>>1][(nt&1)*2], bb[nt>>1][(nt&1)*2+1]);
                }
            }

            // ---- P = exp(s/8 - c_j), split hi/lo, pack as MMA2 A-frags ----
            uint32_t ph01[4], ph23[4], pl01[4], pl23[4];
            #pragma unroll
            for (int nt = 0; nt < 4; nt++) {
                float2 cv = *(const float2*)(smc + CBUF(buf) + (half*32 + nt*8 + (lane&3)*2)*4);
                float p0 = __expf(fmaf(s[nt][0], 0.125f, -cv.x));
                float p1 = __expf(fmaf(s[nt][1], 0.125f, -cv.y));
                float p2 = __expf(fmaf(s[nt][2], 0.125f, -cv.x));
                float p3 = __expf(fmaf(s[nt][3], 0.125f, -cv.y));
                uint16_t h0,l0,h1,l1,h2,l2,h3,l3;
                bfsplit(p0,h0,l0); bfsplit(p1,h1,l1); bfsplit(p2,h2,l2); bfsplit(p3,h3,l3);
                ph01[nt] = (uint32_t)h0 | ((uint32_t)h1 << 16);
                ph23[nt] = (uint32_t)h2 | ((uint32_t)h3 << 16);
                pl01[nt] = (uint32_t)l0 | ((uint32_t)l1 << 16);
                pl23[nt] = (uint32_t)l2 | ((uint32_t)l3 << 16);
            }

            // ---- MMA2: out += P . qT over this 32-j half (k = 2 x 16) ----
            #pragma unroll
            for (int split = 0; split < 3; split++) {
                const uint32_t* p01 = (split == 2) ? pl01 : ph01;
                const uint32_t* p23 = (split == 2) ? pl23 : ph23;
                const uint32_t Bb = sb + ((split == 1) ? QTL(buf) : QTH(buf));
                #pragma unroll
                for (int ks2 = 0; ks2 < 2; ks2++) {
                    uint32_t a2[4] = { p01[2*ks2], p23[2*ks2], p01[2*ks2+1], p23[2*ks2+1] };
                    uint32_t bb[4][4];
                    #pragma unroll
                    for (int ng = 0; ng < 4; ng++)
                        LDSM4(bb[ng][0], bb[ng][1], bb[ng][2], bb[ng][3],
                              Bb + SWZ((ng*16 + brow)*128 + (half*32 + ks2*16 + bcol)*2));
                    #pragma unroll
                    for (int nt2 = 0; nt2 < 8; nt2++)
                        mma_bf16(o[nt2], a2, bb[nt2>>1][(nt2&1)*2], bb[nt2>>1][(nt2&1)*2+1]);
                }
            }
        }

        __syncthreads();
        if (c + 2 < 32) prefetch(c + 2, buf);
        CP_COMMIT();
    }

    const int g = lane >> 2;
    const int t2 = (lane & 3) * 2;
    #pragma unroll
    for (int nt2 = 0; nt2 < 8; nt2++) {
        int row = i0 + w*16 + g;
        int col = nt2*8 + t2;
        *(float2*)(out + ((size_t)b*TT + row)*DD + col) =
            make_float2(o[nt2][0], o[nt2][1]);
        *(float2*)(out + ((size_t)b*TT + row + 8)*DD + col) =
            make_float2(o[nt2][2], o[nt2][3]);
    }
}

// ---------------------------------------------------------------------------
extern "C" void kernel_launch(void* const* d_in, const int* in_sizes, int n_in,
                              void* d_out, int out_size)
{
    const float* x  = (const float*)d_in[0];
    const float* Wq = (const float*)d_in[1];
    const float* bq = (const float*)d_in[2];
    float* out = (float*)d_out;

    const int smem1 = (64*132 + 64*68 + 64) * 4;

    cudaFuncSetAttribute(k1_proj,  cudaFuncAttributeMaxDynamicSharedMemorySize, smem1);
    cudaFuncSetAttribute(ka_stats, cudaFuncAttributeMaxDynamicSharedMemorySize, KA_SMEM);
    cudaFuncSetAttribute(kb_fused, cudaFuncAttributeMaxDynamicSharedMemorySize, KB_SMEM);

    k1_proj<<<NN/128, 128, smem1>>>(x, Wq, bq);
    ka_stats<<<dim3(136, BB), 256, KA_SMEM>>>();
    k3_logz<<<NN/256, 256>>>();
    kb_fused<<<dim3(TT/128, BB), 256, KB_SMEM>>>(out);
}

// round 9
// speedup vs baseline: 1.2851x; 1.2851x over previous
#include <cuda_runtime.h>
#include <cuda_fp16.h>
#include <cstdint>
#include <cstddef>

#define TT 2048
#define BB 16
#define DD 64
#define EE 512
#define NN (BB*TT)

// ---------------------------------------------------------------------------
// Global scratch  (fp16 hi/lo; B-side operands are hi-only)
// ---------------------------------------------------------------------------
__device__ uint16_t g_qh[(size_t)NN * DD];       // q hi  (fp16 bits), row-major [N][64]
__device__ uint16_t g_ql[(size_t)NN * DD];       // q lo
__device__ uint16_t g_qTh[(size_t)NN * DD];      // q^T hi, [b][64][2048]
__device__ float    g_part[(size_t)NN * 16];     // per-(row, j-tile) exp partial sums
__device__ float    g_c[NN];                     // c = log(rowsumexp)

typedef unsigned long long ull;

// ---------------------------------------------------------------------------
// helpers
// ---------------------------------------------------------------------------
__device__ __forceinline__ uint32_t smem_u32(const void* p) {
    uint32_t a;
    asm("{ .reg .u64 t; cvta.to.shared.u64 t, %1; cvt.u32.u64 %0, t; }" : "=r"(a) : "l"(p));
    return a;
}
#define SWZ(o) ((o) ^ (((o) >> 3) & 0x70))

#define LDSM4(r0,r1,r2,r3,a) \
    asm volatile("ldmatrix.sync.aligned.m8n8.x4.shared.b16 {%0,%1,%2,%3}, [%4];" \
        : "=r"(r0),"=r"(r1),"=r"(r2),"=r"(r3) : "r"(a))

__device__ __forceinline__ void mma_f16(float* d, const uint32_t* a,
                                        uint32_t b0, uint32_t b1) {
    asm volatile("mma.sync.aligned.m16n8k16.row.col.f32.f16.f16.f32 "
        "{%0,%1,%2,%3}, {%4,%5,%6,%7}, {%8,%9}, {%0,%1,%2,%3};"
        : "+f"(d[0]),"+f"(d[1]),"+f"(d[2]),"+f"(d[3])
        : "r"(a[0]),"r"(a[1]),"r"(a[2]),"r"(a[3]), "r"(b0),"r"(b1));
}

#define CPA16(dst, src) \
    asm volatile("cp.async.cg.shared.global [%0], [%1], 16;" :: "r"(dst), "l"(src) : "memory")
#define CP_COMMIT() asm volatile("cp.async.commit_group;" ::: "memory")
#define CP_WAIT1()  asm volatile("cp.async.wait_group 1;" ::: "memory")

// fp32 packed-FFMA helpers (K1)
__device__ __forceinline__ ull pk2(float x, float y) {
    ull r; asm("mov.b64 %0,{%1,%2};" : "=l"(r) : "f"(x), "f"(y)); return r;
}
__device__ __forceinline__ void fma2(ull &d, ull a, ull b) {
    asm("fma.rn.f32x2 %0,%1,%2,%0;" : "+l"(d) : "l"(a), "l"(b));
}
__device__ __forceinline__ void upk(ull v, float &x, float &y) {
    asm("mov.b64 {%0,%1},%2;" : "=f"(x), "=f"(y) : "l"(v));
}
__device__ __forceinline__ void hfsplit(float v, uint16_t &h, uint16_t &l) {
    __half hh = __float2half_rn(v);
    float r = v - __half2float(hh);
    __half ll = __float2half_rn(r);
    h = __half_as_ushort(hh);
    l = __half_as_ushort(ll);
}

// ---------------------------------------------------------------------------
// K1: q = x @ Wq + bq  -> fp16 hi/lo row-major + transposed hi  (FFMA2 core)
// ---------------------------------------------------------------------------
__global__ __launch_bounds__(128) void k1_proj(
    const float* __restrict__ x, const float* __restrict__ Wq,
    const float* __restrict__ bq)
{
    extern __shared__ float sm[];
    float (*xsT)[132] = (float(*)[132])sm;
    float (*ws)[68]   = (float(*)[68])(sm + 64*132);
    float *bs = sm + 64*132 + 64*68;

    const int tid = threadIdx.x;
    const int r0 = blockIdx.x * 128;
    if (tid < 64) bs[tid] = bq[tid];

    const int tx = tid & 7, ty = tid >> 3;
    ull acc[8][4];
    #pragma unroll
    for (int r = 0; r < 8; r++)
        #pragma unroll
        for (int c = 0; c < 4; c++) acc[r][c] = 0ull;

    for (int kc = 0; kc < EE; kc += 64) {
        __syncthreads();
        #pragma unroll
        for (int idx = tid; idx < 1024; idx += 128) {
            int k = idx >> 4, qd = idx & 15;
            ((float4*)&ws[k][0])[qd] = ((const float4*)(Wq + (size_t)(kc + k) * DD))[qd];
        }
        const float* xr = x + (size_t)(r0 + tid) * EE + kc;
        #pragma unroll
        for (int u = 0; u < 16; u++) {
            float4 v = *(const float4*)(xr + u * 4);
            xsT[u*4+0][tid] = v.x; xsT[u*4+1][tid] = v.y;
            xsT[u*4+2][tid] = v.z; xsT[u*4+3][tid] = v.w;
        }
        __syncthreads();
        #pragma unroll 8
        for (int k = 0; k < 64; k++) {
            float4 a0 = *(const float4*)&xsT[k][ty*8];
            float4 a1 = *(const float4*)&xsT[k][ty*8+4];
            float4 b0 = *(const float4*)&ws[k][tx*4];
            float4 b1 = *(const float4*)&ws[k][32 + tx*4];
            ull bb0 = pk2(b0.x,b0.y), bb1 = pk2(b0.z,b0.w);
            ull bb2 = pk2(b1.x,b1.y), bb3 = pk2(b1.z,b1.w);
            float av[8] = {a0.x,a0.y,a0.z,a0.w,a1.x,a1.y,a1.z,a1.w};
            #pragma unroll
            for (int r = 0; r < 8; r++) {
                ull ar = pk2(av[r], av[r]);
                fma2(acc[r][0], ar, bb0); fma2(acc[r][1], ar, bb1);
                fma2(acc[r][2], ar, bb2); fma2(acc[r][3], ar, bb3);
            }
        }
    }
    __syncthreads();
    float (*qt)[132] = (float(*)[132])sm;   // [d][row_local]
    const int b = r0 >> 11;
    const int t0l = r0 & (TT - 1);

    #pragma unroll
    for (int r = 0; r < 8; r++) {
        float f[8];
        upk(acc[r][0], f[0], f[1]); upk(acc[r][1], f[2], f[3]);
        upk(acc[r][2], f[4], f[5]); upk(acc[r][3], f[6], f[7]);
        const int rl = ty*8 + r;
        const int row = r0 + rl;
        float v[8];
        #pragma unroll
        for (int c = 0; c < 4; c++) {
            v[c]   = f[c]   + bs[tx*4 + c];
            v[4+c] = f[4+c] + bs[32 + tx*4 + c];
        }
        #pragma unroll
        for (int c = 0; c < 4; c++) {
            qt[tx*4 + c][rl]      = v[c];
            qt[32 + tx*4 + c][rl] = v[4+c];
        }
        uint16_t h[8], l[8];
        #pragma unroll
        for (int c = 0; c < 8; c++) hfsplit(v[c], h[c], l[c]);
        uint2 uh0, ul0, uh1, ul1;
        uh0.x = (uint32_t)h[0] | ((uint32_t)h[1] << 16); uh0.y = (uint32_t)h[2] | ((uint32_t)h[3] << 16);
        uh1.x = (uint32_t)h[4] | ((uint32_t)h[5] << 16); uh1.y = (uint32_t)h[6] | ((uint32_t)h[7] << 16);
        ul0.x = (uint32_t)l[0] | ((uint32_t)l[1] << 16); ul0.y = (uint32_t)l[2] | ((uint32_t)l[3] << 16);
        ul1.x = (uint32_t)l[4] | ((uint32_t)l[5] << 16); ul1.y = (uint32_t)l[6] | ((uint32_t)l[7] << 16);
        *(uint2*)(g_qh + (size_t)row*DD + tx*4)      = uh0;
        *(uint2*)(g_qh + (size_t)row*DD + 32 + tx*4) = uh1;
        *(uint2*)(g_ql + (size_t)row*DD + tx*4)      = ul0;
        *(uint2*)(g_ql + (size_t)row*DD + 32 + tx*4) = ul1;
    }
    __syncthreads();
    for (int idx = tid; idx < 64*64; idx += 128) {
        int d = idx >> 6, tp = idx & 63;
        float v0 = qt[d][tp*2], v1 = qt[d][tp*2 + 1];
        uint16_t h0 = __half_as_ushort(__float2half_rn(v0));
        uint16_t h1 = __half_as_ushort(__float2half_rn(v1));
        size_t off = ((size_t)b*DD + d)*TT + t0l + tp*2;
        *(uint32_t*)(g_qTh + off) = (uint32_t)h0 | ((uint32_t)h1 << 16);
    }
}

// ---------------------------------------------------------------------------
// KA: stats only. S̃ = q_i(full) . q_j(hi)^T /8 via 2 fp16 MMAs; exp partial
// row & column sums -> g_part.  grid (136, 16), 256 threads.
// smem: A_h 16K, A_l 16K, B_h 16K + stats 3K
// ---------------------------------------------------------------------------
#define KA_SMEM (49152 + 2048 + 1024)

__global__ __launch_bounds__(256) void ka_stats()
{
    extern __shared__ char smc[];
    float* rowpart = (float*)(smc + 49152);            // [4 wn][128 rows]
    float* colpart = (float*)(smc + 49152 + 2048);     // [2 wm][128 cols]
    const uint32_t sb = smem_u32(smc);
    const int tid = threadIdx.x, lane = tid & 31, w = tid >> 5;
    const int b = blockIdx.y;
    int jy = 0, rem = blockIdx.x;
    while (rem >= 16 - jy) { rem -= 16 - jy; jy++; }
    const int ix = jy + rem;
    const int i0 = ix * 128, j0 = jy * 128;

    // 3 operand tiles: A_h (rows i0), A_l (rows i0), B_h (rows j0)
    #pragma unroll
    for (int it = 0; it < 12; it++) {
        int idx = it*256 + tid;
        int tile = idx >> 10;
        int r = (idx >> 3) & 127, ch = idx & 7;
        const uint16_t* src = (tile == 1) ? g_ql : g_qh;
        int grow = (tile < 2) ? (i0 + r) : (j0 + r);
        int dst  = tile * 16384;
        uint4 v = *(const uint4*)(src + ((size_t)(b*TT + grow))*DD + ch*8);
        *(uint4*)(smc + dst + SWZ(r*128 + ch*16)) = v;
    }
    __syncthreads();

    const int wm = w >> 2, wn = w & 3;
    const int arow = lane & 15;
    const int acol = (lane & 16) >> 1;
    const int brow = (lane & 7) | ((lane & 16) >> 1);
    const int bcol = lane & 8;

    float d[16][4];
    #pragma unroll
    for (int t = 0; t < 16; t++)
        #pragma unroll
        for (int e = 0; e < 4; e++) d[t][e] = 0.f;

    #pragma unroll
    for (int split = 0; split < 2; split++) {
        const uint32_t Ab = sb + split * 16384;
        const uint32_t Bb = sb + 32768;
        #pragma unroll
        for (int ks = 0; ks < 4; ks++) {
            uint32_t a[4][4];
            #pragma unroll
            for (int mt = 0; mt < 4; mt++)
                LDSM4(a[mt][0], a[mt][1], a[mt][2], a[mt][3],
                      Ab + SWZ((wm*64 + mt*16 + arow)*128 + (ks*16 + acol)*2));
            uint32_t bb[2][4];
            #pragma unroll
            for (int ng = 0; ng < 2; ng++)
                LDSM4(bb[ng][0], bb[ng][1], bb[ng][2], bb[ng][3],
                      Bb + SWZ((wn*32 + ng*16 + brow)*128 + (ks*16 + bcol)*2));
            #pragma unroll
            for (int mt = 0; mt < 4; mt++)
                #pragma unroll
                for (int nt = 0; nt < 4; nt++)
                    mma_f16(d[mt*4+nt], a[mt],
                            bb[nt>>1][(nt&1)*2], bb[nt>>1][(nt&1)*2+1]);
        }
    }

    const int r_i = lane >> 2;
    const bool diag = (ix == jy);

    float rp[4][2], cp[4][2];
    #pragma unroll
    for (int t = 0; t < 4; t++) { rp[t][0]=rp[t][1]=0.f; cp[t][0]=cp[t][1]=0.f; }

    #pragma unroll
    for (int mt = 0; mt < 4; mt++) {
        #pragma unroll
        for (int nt = 0; nt < 4; nt++) {
            float e0 = __expf(d[mt*4+nt][0]*0.125f);
            float e1 = __expf(d[mt*4+nt][1]*0.125f);
            float e2 = __expf(d[mt*4+nt][2]*0.125f);
            float e3 = __expf(d[mt*4+nt][3]*0.125f);
            rp[mt][0] += e0 + e1;  rp[mt][1] += e2 + e3;
            cp[nt][0] += e0 + e2;  cp[nt][1] += e1 + e3;
        }
    }
    #pragma unroll
    for (int mt = 0; mt < 4; mt++) {
        float r0 = rp[mt][0], r1 = rp[mt][1];
        r0 += __shfl_xor_sync(0xffffffffu, r0, 1); r0 += __shfl_xor_sync(0xffffffffu, r0, 2);
        r1 += __shfl_xor_sync(0xffffffffu, r1, 1); r1 += __shfl_xor_sync(0xffffffffu, r1, 2);
        if ((lane & 3) == 0) {
            int rl = wm*64 + mt*16 + r_i;
            rowpart[wn*128 + rl]     = r0;
            rowpart[wn*128 + rl + 8] = r1;
        }
    }
    #pragma unroll
    for (int nt = 0; nt < 4; nt++) {
        float c0 = cp[nt][0], c1 = cp[nt][1];
        c0 += __shfl_xor_sync(0xffffffffu, c0, 4); c0 += __shfl_xor_sync(0xffffffffu, c0, 8);
        c0 += __shfl_xor_sync(0xffffffffu, c0, 16);
        c1 += __shfl_xor_sync(0xffffffffu, c1, 4); c1 += __shfl_xor_sync(0xffffffffu, c1, 8);
        c1 += __shfl_xor_sync(0xffffffffu, c1, 16);
        if (lane < 4) {
            int cl = wn*32 + nt*8 + lane*2;
            colpart[wm*128 + cl]     = c0;
            colpart[wm*128 + cl + 1] = c1;
        }
    }
    __syncthreads();

    if (tid < 128) {
        float rs = rowpart[tid] + rowpart[128+tid] + rowpart[256+tid] + rowpart[384+tid];
        g_part[((size_t)(b*TT + i0 + tid))*16 + jy] = rs;
        if (!diag) {
            float cs = colpart[tid] + colpart[128+tid];
            g_part[((size_t)(b*TT + j0 + tid))*16 + ix] = cs;
        }
    }
}

// ---------------------------------------------------------------------------
// K3': c[n] = log( sum of 16 partials )
// ---------------------------------------------------------------------------
__global__ __launch_bounds__(256) void k3_logz()
{
    const int n = blockIdx.x * 256 + threadIdx.x;
    const float* p = g_part + (size_t)n * 16;
    float4 a = *(const float4*)(p);
    float4 b = *(const float4*)(p + 4);
    float4 c = *(const float4*)(p + 8);
    float4 e = *(const float4*)(p + 12);
    float s = a.x + a.y + a.z + a.w;
    s += b.x + b.y + b.z + b.w;
    s += c.x + c.y + c.z + c.w;
    s += e.x + e.y + e.z + e.w;
    g_c[n] = logf(s);
}

// ---------------------------------------------------------------------------
// KB: fused out = P.q, S recomputed (2 fp16 MMAs), P register-resident,
// MMA2 = (Ph + Pl).qTh (2 MMAs). B-side lo operands never loaded.
// grid (16 i-tiles of 128, 16 b), 256 threads (8 warps, each m16), 2 CTAs/SM.
// ---------------------------------------------------------------------------
#define KB_STRIDE 16640
#define QJH(buf) ((buf)*KB_STRIDE)
#define QTH(buf) ((buf)*KB_STRIDE + 8192)
#define CBUF(buf) ((buf)*KB_STRIDE + 16384)
#define QI_H (2*KB_STRIDE)
#define QI_L (2*KB_STRIDE + 16384)
#define KB_SMEM (2*KB_STRIDE + 32768)

__global__ __launch_bounds__(256, 2) void kb_fused(float* __restrict__ out)
{
    extern __shared__ char smc[];
    const uint32_t sb = smem_u32(smc);
    const int tid = threadIdx.x, lane = tid & 31, w = tid >> 5;
    const int i0 = blockIdx.x * 128, b = blockIdx.y;

    const uint16_t* qh  = g_qh  + (size_t)b * TT * DD;
    const uint16_t* ql  = g_ql  + (size_t)b * TT * DD;
    const uint16_t* qTh = g_qTh + (size_t)b * DD * TT;
    const float*    cb  = g_c + b * TT;

    // --- stage q_i [128][64] hi/lo into resident smem tiles ---
    #pragma unroll
    for (int it = 0; it < 4; it++) {
        int idx = it*256 + tid;           // 1024: 128 rows x 8 segs
        int r = idx >> 3, seg = idx & 7;
        *(uint4*)(smc + QI_H + SWZ(r*128 + seg*16)) =
            *(const uint4*)(qh + (size_t)(i0 + r)*DD + seg*8);
        *(uint4*)(smc + QI_L + SWZ(r*128 + seg*16)) =
            *(const uint4*)(ql + (size_t)(i0 + r)*DD + seg*8);
    }

    auto prefetch = [&](int c, int buf) {
        const int j0c = c * 64;
        #pragma unroll
        for (int k2 = 0; k2 < 2; k2++) {
            int idx = k2*256 + tid;       // 512: 64 rows x 8 segs
            int r = idx >> 3, seg = idx & 7;
            CPA16(sb + QJH(buf) + SWZ(r*128 + seg*16),
                  (const void*)(qh + (size_t)(j0c + r)*DD + seg*8));
            CPA16(sb + QTH(buf) + SWZ(r*128 + seg*16),
                  (const void*)(qTh + (size_t)r*TT + j0c + seg*8));
        }
        if (tid < 16)
            CPA16(sb + CBUF(buf) + tid*16, (const void*)(cb + j0c + tid*4));
    };

    prefetch(0, 0); CP_COMMIT();
    prefetch(1, 1); CP_COMMIT();
    __syncthreads();   // q_i staging visible to all warps

    const int arow = lane & 15;
    const int acol = (lane & 16) >> 1;
    const int brow = (lane & 7) | ((lane & 16) >> 1);
    const int bcol = lane & 8;

    float o[8][4];
    #pragma unroll
    for (int t = 0; t < 8; t++)
        #pragma unroll
        for (int e = 0; e < 4; e++) o[t][e] = 0.f;

    for (int c = 0; c < 32; c++) {
        const int buf = c & 1;
        CP_WAIT1();
        __syncthreads();

        #pragma unroll
        for (int half = 0; half < 2; half++) {
            // ---- MMA1: s = (qi_h + qi_l) . qj_h^T for 32 j ----
            float s[4][4];
            #pragma unroll
            for (int t = 0; t < 4; t++)
                #pragma unroll
                for (int e = 0; e < 4; e++) s[t][e] = 0.f;

            #pragma unroll
            for (int split = 0; split < 2; split++) {
                const uint32_t Asrc = sb + (split ? QI_L : QI_H);
                const uint32_t Bb = sb + QJH(buf);
                #pragma unroll
                for (int ks = 0; ks < 4; ks++) {
                    uint32_t a[4];
                    LDSM4(a[0], a[1], a[2], a[3],
                          Asrc + SWZ((w*16 + arow)*128 + (ks*16 + acol)*2));
                    uint32_t bb[2][4];
                    #pragma unroll
                    for (int ng = 0; ng < 2; ng++)
                        LDSM4(bb[ng][0], bb[ng][1], bb[ng][2], bb[ng][3],
                              Bb + SWZ((half*32 + ng*16 + brow)*128 + (ks*16 + bcol)*2));
                    #pragma unroll
                    for (int nt = 0; nt < 4; nt++)
                        mma_f16(s[nt], a, bb[nt>>1][(nt&1)*2], bb[nt>>1][(nt&1)*2+1]);
                }
            }

            // ---- P = exp(s/8 - c_j), split fp16 hi/lo, pack as A-frags ----
            uint32_t ph01[4], ph23[4], pl01[4], pl23[4];
            #pragma unroll
            for (int nt = 0; nt < 4; nt++) {
                float2 cv = *(const float2*)(smc + CBUF(buf) + (half*32 + nt*8 + (lane&3)*2)*4);
                float p0 = __expf(fmaf(s[nt][0], 0.125f, -cv.x));
                float p1 = __expf(fmaf(s[nt][1], 0.125f, -cv.y));
                float p2 = __expf(fmaf(s[nt][2], 0.125f, -cv.x));
                float p3 = __expf(fmaf(s[nt][3], 0.125f, -cv.y));
                uint16_t h0,l0,h1,l1,h2,l2,h3,l3;
                hfsplit(p0,h0,l0); hfsplit(p1,h1,l1); hfsplit(p2,h2,l2); hfsplit(p3,h3,l3);
                ph01[nt] = (uint32_t)h0 | ((uint32_t)h1 << 16);
                ph23[nt] = (uint32_t)h2 | ((uint32_t)h3 << 16);
                pl01[nt] = (uint32_t)l0 | ((uint32_t)l1 << 16);
                pl23[nt] = (uint32_t)l2 | ((uint32_t)l3 << 16);
            }

            // ---- MMA2: out += (Ph + Pl) . qTh over this 32-j half ----
            #pragma unroll
            for (int split = 0; split < 2; split++) {
                const uint32_t* p01 = split ? pl01 : ph01;
                const uint32_t* p23 = split ? pl23 : ph23;
                const uint32_t Bb = sb + QTH(buf);
                #pragma unroll
                for (int ks2 = 0; ks2 < 2; ks2++) {
                    uint32_t a2[4] = { p01[2*ks2], p23[2*ks2], p01[2*ks2+1], p23[2*ks2+1] };
                    uint32_t bb[4][4];
                    #pragma unroll
                    for (int ng = 0; ng < 4; ng++)
                        LDSM4(bb[ng][0], bb[ng][1], bb[ng][2], bb[ng][3],
                              Bb + SWZ((ng*16 + brow)*128 + (half*32 + ks2*16 + bcol)*2));
                    #pragma unroll
                    for (int nt2 = 0; nt2 < 8; nt2++)
                        mma_f16(o[nt2], a2, bb[nt2>>1][(nt2&1)*2], bb[nt2>>1][(nt2&1)*2+1]);
                }
            }
        }

        __syncthreads();
        if (c + 2 < 32) prefetch(c + 2, buf);
        CP_COMMIT();
    }

    const int g = lane >> 2;
    const int t2 = (lane & 3) * 2;
    #pragma unroll
    for (int nt2 = 0; nt2 < 8; nt2++) {
        int row = i0 + w*16 + g;
        int col = nt2*8 + t2;
        *(float2*)(out + ((size_t)b*TT + row)*DD + col) =
            make_float2(o[nt2][0], o[nt2][1]);
        *(float2*)(out + ((size_t)b*TT + row + 8)*DD + col) =
            make_float2(o[nt2][2], o[nt2][3]);
    }
}

// ---------------------------------------------------------------------------
extern "C" void kernel_launch(void* const* d_in, const int* in_sizes, int n_in,
                              void* d_out, int out_size)
{
    const float* x  = (const float*)d_in[0];
    const float* Wq = (const float*)d_in[1];
    const float* bq = (const float*)d_in[2];
    float* out = (float*)d_out;

    const int smem1 = (64*132 + 64*68 + 64) * 4;

    cudaFuncSetAttribute(k1_proj,  cudaFuncAttributeMaxDynamicSharedMemorySize, smem1);
    cudaFuncSetAttribute(ka_stats, cudaFuncAttributeMaxDynamicSharedMemorySize, KA_SMEM);
    cudaFuncSetAttribute(kb_fused, cudaFuncAttributeMaxDynamicSharedMemorySize, KB_SMEM);

    k1_proj<<<NN/128, 128, smem1>>>(x, Wq, bq);
    ka_stats<<<dim3(136, BB), 256, KA_SMEM>>>();
    k3_logz<<<NN/256, 256>>>();
    kb_fused<<<dim3(TT/128, BB), 256, KB_SMEM>>>(out);
}

// round 10
// speedup vs baseline: 1.7559x; 1.3663x over previous
#include <cuda_runtime.h>
#include <cuda_fp16.h>
#include <cstdint>
#include <cstddef>

#define TT 2048
#define BB 16
#define DD 64
#define EE 512
#define NN (BB*TT)

// ---------------------------------------------------------------------------
// Global scratch  (all MMA operands are fp16 hi-only; softmax self-consistent)
// ---------------------------------------------------------------------------
__device__ uint16_t g_qh[(size_t)NN * DD];       // q hi  (fp16 bits), row-major [N][64]
__device__ uint16_t g_qTh[(size_t)NN * DD];      // q^T hi, [b][64][2048]
__device__ float    g_part[(size_t)NN * 16];     // per-(row, j-tile) exp partial sums
__device__ float    g_c[NN];                     // c = log(rowsumexp)

typedef unsigned long long ull;

// ---------------------------------------------------------------------------
// helpers
// ---------------------------------------------------------------------------
__device__ __forceinline__ uint32_t smem_u32(const void* p) {
    uint32_t a;
    asm("{ .reg .u64 t; cvta.to.shared.u64 t, %1; cvt.u32.u64 %0, t; }" : "=r"(a) : "l"(p));
    return a;
}
#define SWZ(o) ((o) ^ (((o) >> 3) & 0x70))

#define LDSM4(r0,r1,r2,r3,a) \
    asm volatile("ldmatrix.sync.aligned.m8n8.x4.shared.b16 {%0,%1,%2,%3}, [%4];" \
        : "=r"(r0),"=r"(r1),"=r"(r2),"=r"(r3) : "r"(a))

__device__ __forceinline__ void mma_f16(float* d, const uint32_t* a,
                                        uint32_t b0, uint32_t b1) {
    asm volatile("mma.sync.aligned.m16n8k16.row.col.f32.f16.f16.f32 "
        "{%0,%1,%2,%3}, {%4,%5,%6,%7}, {%8,%9}, {%0,%1,%2,%3};"
        : "+f"(d[0]),"+f"(d[1]),"+f"(d[2]),"+f"(d[3])
        : "r"(a[0]),"r"(a[1]),"r"(a[2]),"r"(a[3]), "r"(b0),"r"(b1));
}

#define CPA16(dst, src) \
    asm volatile("cp.async.cg.shared.global [%0], [%1], 16;" :: "r"(dst), "l"(src) : "memory")
#define CP_COMMIT() asm volatile("cp.async.commit_group;" ::: "memory")
#define CP_WAIT1()  asm volatile("cp.async.wait_group 1;" ::: "memory")

// fp32 packed-FFMA helpers (K1)
__device__ __forceinline__ ull pk2(float x, float y) {
    ull r; asm("mov.b64 %0,{%1,%2};" : "=l"(r) : "f"(x), "f"(y)); return r;
}
__device__ __forceinline__ void fma2(ull &d, ull a, ull b) {
    asm("fma.rn.f32x2 %0,%1,%2,%0;" : "+l"(d) : "l"(a), "l"(b));
}
__device__ __forceinline__ void upk(ull v, float &x, float &y) {
    asm("mov.b64 {%0,%1},%2;" : "=f"(x), "=f"(y) : "l"(v));
}

// ---------------------------------------------------------------------------
// K1: q = x @ Wq + bq  -> fp16 row-major + transposed  (FFMA2 core)
// ---------------------------------------------------------------------------
__global__ __launch_bounds__(128) void k1_proj(
    const float* __restrict__ x, const float* __restrict__ Wq,
    const float* __restrict__ bq)
{
    extern __shared__ float sm[];
    float (*xsT)[132] = (float(*)[132])sm;
    float (*ws)[68]   = (float(*)[68])(sm + 64*132);
    float *bs = sm + 64*132 + 64*68;

    const int tid = threadIdx.x;
    const int r0 = blockIdx.x * 128;
    if (tid < 64) bs[tid] = bq[tid];

    const int tx = tid & 7, ty = tid >> 3;
    ull acc[8][4];
    #pragma unroll
    for (int r = 0; r < 8; r++)
        #pragma unroll
        for (int c = 0; c < 4; c++) acc[r][c] = 0ull;

    for (int kc = 0; kc < EE; kc += 64) {
        __syncthreads();
        #pragma unroll
        for (int idx = tid; idx < 1024; idx += 128) {
            int k = idx >> 4, qd = idx & 15;
            ((float4*)&ws[k][0])[qd] = ((const float4*)(Wq + (size_t)(kc + k) * DD))[qd];
        }
        const float* xr = x + (size_t)(r0 + tid) * EE + kc;
        #pragma unroll
        for (int u = 0; u < 16; u++) {
            float4 v = *(const float4*)(xr + u * 4);
            xsT[u*4+0][tid] = v.x; xsT[u*4+1][tid] = v.y;
            xsT[u*4+2][tid] = v.z; xsT[u*4+3][tid] = v.w;
        }
        __syncthreads();
        #pragma unroll 8
        for (int k = 0; k < 64; k++) {
            float4 a0 = *(const float4*)&xsT[k][ty*8];
            float4 a1 = *(const float4*)&xsT[k][ty*8+4];
            float4 b0 = *(const float4*)&ws[k][tx*4];
            float4 b1 = *(const float4*)&ws[k][32 + tx*4];
            ull bb0 = pk2(b0.x,b0.y), bb1 = pk2(b0.z,b0.w);
            ull bb2 = pk2(b1.x,b1.y), bb3 = pk2(b1.z,b1.w);
            float av[8] = {a0.x,a0.y,a0.z,a0.w,a1.x,a1.y,a1.z,a1.w};
            #pragma unroll
            for (int r = 0; r < 8; r++) {
                ull ar = pk2(av[r], av[r]);
                fma2(acc[r][0], ar, bb0); fma2(acc[r][1], ar, bb1);
                fma2(acc[r][2], ar, bb2); fma2(acc[r][3], ar, bb3);
            }
        }
    }
    __syncthreads();
    float (*qt)[132] = (float(*)[132])sm;   // [d][row_local]
    const int b = r0 >> 11;
    const int t0l = r0 & (TT - 1);

    #pragma unroll
    for (int r = 0; r < 8; r++) {
        float f[8];
        upk(acc[r][0], f[0], f[1]); upk(acc[r][1], f[2], f[3]);
        upk(acc[r][2], f[4], f[5]); upk(acc[r][3], f[6], f[7]);
        const int rl = ty*8 + r;
        const int row = r0 + rl;
        float v[8];
        #pragma unroll
        for (int c = 0; c < 4; c++) {
            v[c]   = f[c]   + bs[tx*4 + c];
            v[4+c] = f[4+c] + bs[32 + tx*4 + c];
        }
        #pragma unroll
        for (int c = 0; c < 4; c++) {
            qt[tx*4 + c][rl]      = v[c];
            qt[32 + tx*4 + c][rl] = v[4+c];
        }
        uint16_t h[8];
        #pragma unroll
        for (int c = 0; c < 8; c++) h[c] = __half_as_ushort(__float2half_rn(v[c]));
        uint2 uh0, uh1;
        uh0.x = (uint32_t)h[0] | ((uint32_t)h[1] << 16); uh0.y = (uint32_t)h[2] | ((uint32_t)h[3] << 16);
        uh1.x = (uint32_t)h[4] | ((uint32_t)h[5] << 16); uh1.y = (uint32_t)h[6] | ((uint32_t)h[7] << 16);
        *(uint2*)(g_qh + (size_t)row*DD + tx*4)      = uh0;
        *(uint2*)(g_qh + (size_t)row*DD + 32 + tx*4) = uh1;
    }
    __syncthreads();
    for (int idx = tid; idx < 64*64; idx += 128) {
        int d = idx >> 6, tp = idx & 63;
        float v0 = qt[d][tp*2], v1 = qt[d][tp*2 + 1];
        uint16_t h0 = __half_as_ushort(__float2half_rn(v0));
        uint16_t h1 = __half_as_ushort(__float2half_rn(v1));
        size_t off = ((size_t)b*DD + d)*TT + t0l + tp*2;
        *(uint32_t*)(g_qTh + off) = (uint32_t)h0 | ((uint32_t)h1 << 16);
    }
}

// ---------------------------------------------------------------------------
// KA: stats only. S̃ = qh_i . qh_j^T /8 (1 fp16 MMA pass, bitwise-consistent
// with KB's recompute); exp partial row & col sums -> g_part.
// grid (136, 16), 256 threads.
// ---------------------------------------------------------------------------
#define KA_SMEM (32768 + 2048 + 1024)

__global__ __launch_bounds__(256) void ka_stats()
{
    extern __shared__ char smc[];
    float* rowpart = (float*)(smc + 32768);            // [4 wn][128 rows]
    float* colpart = (float*)(smc + 32768 + 2048);     // [2 wm][128 cols]
    const uint32_t sb = smem_u32(smc);
    const int tid = threadIdx.x, lane = tid & 31, w = tid >> 5;
    const int b = blockIdx.y;
    int jy = 0, rem = blockIdx.x;
    while (rem >= 16 - jy) { rem -= 16 - jy; jy++; }
    const int ix = jy + rem;
    const int i0 = ix * 128, j0 = jy * 128;

    // 2 operand tiles: A_h (rows i0), B_h (rows j0)
    #pragma unroll
    for (int it = 0; it < 8; it++) {
        int idx = it*256 + tid;
        int tile = idx >> 10;
        int r = (idx >> 3) & 127, ch = idx & 7;
        int grow = (tile == 0) ? (i0 + r) : (j0 + r);
        uint4 v = *(const uint4*)(g_qh + ((size_t)(b*TT + grow))*DD + ch*8);
        *(uint4*)(smc + tile*16384 + SWZ(r*128 + ch*16)) = v;
    }
    __syncthreads();

    const int wm = w >> 2, wn = w & 3;
    const int arow = lane & 15;
    const int acol = (lane & 16) >> 1;
    const int brow = (lane & 7) | ((lane & 16) >> 1);
    const int bcol = lane & 8;

    float d[16][4];
    #pragma unroll
    for (int t = 0; t < 16; t++)
        #pragma unroll
        for (int e = 0; e < 4; e++) d[t][e] = 0.f;

    {
        const uint32_t Ab = sb;
        const uint32_t Bb = sb + 16384;
        #pragma unroll
        for (int ks = 0; ks < 4; ks++) {
            uint32_t a[4][4];
            #pragma unroll
            for (int mt = 0; mt < 4; mt++)
                LDSM4(a[mt][0], a[mt][1], a[mt][2], a[mt][3],
                      Ab + SWZ((wm*64 + mt*16 + arow)*128 + (ks*16 + acol)*2));
            uint32_t bb[2][4];
            #pragma unroll
            for (int ng = 0; ng < 2; ng++)
                LDSM4(bb[ng][0], bb[ng][1], bb[ng][2], bb[ng][3],
                      Bb + SWZ((wn*32 + ng*16 + brow)*128 + (ks*16 + bcol)*2));
            #pragma unroll
            for (int mt = 0; mt < 4; mt++)
                #pragma unroll
                for (int nt = 0; nt < 4; nt++)
                    mma_f16(d[mt*4+nt], a[mt],
                            bb[nt>>1][(nt&1)*2], bb[nt>>1][(nt&1)*2+1]);
        }
    }

    const int r_i = lane >> 2;
    const bool diag = (ix == jy);

    float rp[4][2], cp[4][2];
    #pragma unroll
    for (int t = 0; t < 4; t++) { rp[t][0]=rp[t][1]=0.f; cp[t][0]=cp[t][1]=0.f; }

    #pragma unroll
    for (int mt = 0; mt < 4; mt++) {
        #pragma unroll
        for (int nt = 0; nt < 4; nt++) {
            float e0 = __expf(d[mt*4+nt][0]*0.125f);
            float e1 = __expf(d[mt*4+nt][1]*0.125f);
            float e2 = __expf(d[mt*4+nt][2]*0.125f);
            float e3 = __expf(d[mt*4+nt][3]*0.125f);
            rp[mt][0] += e0 + e1;  rp[mt][1] += e2 + e3;
            cp[nt][0] += e0 + e2;  cp[nt][1] += e1 + e3;
        }
    }
    #pragma unroll
    for (int mt = 0; mt < 4; mt++) {
        float r0 = rp[mt][0], r1 = rp[mt][1];
        r0 += __shfl_xor_sync(0xffffffffu, r0, 1); r0 += __shfl_xor_sync(0xffffffffu, r0, 2);
        r1 += __shfl_xor_sync(0xffffffffu, r1, 1); r1 += __shfl_xor_sync(0xffffffffu, r1, 2);
        if ((lane & 3) == 0) {
            int rl = wm*64 + mt*16 + r_i;
            rowpart[wn*128 + rl]     = r0;
            rowpart[wn*128 + rl + 8] = r1;
        }
    }
    #pragma unroll
    for (int nt = 0; nt < 4; nt++) {
        float c0 = cp[nt][0], c1 = cp[nt][1];
        c0 += __shfl_xor_sync(0xffffffffu, c0, 4); c0 += __shfl_xor_sync(0xffffffffu, c0, 8);
        c0 += __shfl_xor_sync(0xffffffffu, c0, 16);
        c1 += __shfl_xor_sync(0xffffffffu, c1, 4); c1 += __shfl_xor_sync(0xffffffffu, c1, 8);
        c1 += __shfl_xor_sync(0xffffffffu, c1, 16);
        if (lane < 4) {
            int cl = wn*32 + nt*8 + lane*2;
            colpart[wm*128 + cl]     = c0;
            colpart[wm*128 + cl + 1] = c1;
        }
    }
    __syncthreads();

    if (tid < 128) {
        float rs = rowpart[tid] + rowpart[128+tid] + rowpart[256+tid] + rowpart[384+tid];
        g_part[((size_t)(b*TT + i0 + tid))*16 + jy] = rs;
        if (!diag) {
            float cs = colpart[tid] + colpart[128+tid];
            g_part[((size_t)(b*TT + j0 + tid))*16 + ix] = cs;
        }
    }
}

// ---------------------------------------------------------------------------
// K3': c[n] = log( sum of 16 partials )
// ---------------------------------------------------------------------------
__global__ __launch_bounds__(256) void k3_logz()
{
    const int n = blockIdx.x * 256 + threadIdx.x;
    const float* p = g_part + (size_t)n * 16;
    float4 a = *(const float4*)(p);
    float4 b = *(const float4*)(p + 4);
    float4 c = *(const float4*)(p + 8);
    float4 e = *(const float4*)(p + 12);
    float s = a.x + a.y + a.z + a.w;
    s += b.x + b.y + b.z + b.w;
    s += c.x + c.y + c.z + c.w;
    s += e.x + e.y + e.z + e.w;
    g_c[n] = logf(s);
}

// ---------------------------------------------------------------------------
// KB: fused out = P.q; S̃ recomputed (1 fp16 MMA pass, consistent with KA),
// P rounded to fp16 (no split), out += P.qTh (1 MMA pass).
// grid (16 i-tiles of 128, 16 b), 256 threads (8 warps, each m16), 2 CTAs/SM.
// ---------------------------------------------------------------------------
#define KB_STRIDE 16640
#define QJH(buf) ((buf)*KB_STRIDE)
#define QTH(buf) ((buf)*KB_STRIDE + 8192)
#define CBUF(buf) ((buf)*KB_STRIDE + 16384)
#define QI_H (2*KB_STRIDE)
#define KB_SMEM (2*KB_STRIDE + 16384)

__global__ __launch_bounds__(256, 2) void kb_fused(float* __restrict__ out)
{
    extern __shared__ char smc[];
    const uint32_t sb = smem_u32(smc);
    const int tid = threadIdx.x, lane = tid & 31, w = tid >> 5;
    const int i0 = blockIdx.x * 128, b = blockIdx.y;

    const uint16_t* qh  = g_qh  + (size_t)b * TT * DD;
    const uint16_t* qTh = g_qTh + (size_t)b * DD * TT;
    const float*    cb  = g_c + b * TT;

    // --- stage q_i [128][64] hi into resident smem tile ---
    #pragma unroll
    for (int it = 0; it < 4; it++) {
        int idx = it*256 + tid;           // 1024: 128 rows x 8 segs
        int r = idx >> 3, seg = idx & 7;
        *(uint4*)(smc + QI_H + SWZ(r*128 + seg*16)) =
            *(const uint4*)(qh + (size_t)(i0 + r)*DD + seg*8);
    }

    auto prefetch = [&](int c, int buf) {
        const int j0c = c * 64;
        #pragma unroll
        for (int k2 = 0; k2 < 2; k2++) {
            int idx = k2*256 + tid;       // 512: 64 rows x 8 segs
            int r = idx >> 3, seg = idx & 7;
            CPA16(sb + QJH(buf) + SWZ(r*128 + seg*16),
                  (const void*)(qh + (size_t)(j0c + r)*DD + seg*8));
            CPA16(sb + QTH(buf) + SWZ(r*128 + seg*16),
                  (const void*)(qTh + (size_t)r*TT + j0c + seg*8));
        }
        if (tid < 16)
            CPA16(sb + CBUF(buf) + tid*16, (const void*)(cb + j0c + tid*4));
    };

    prefetch(0, 0); CP_COMMIT();
    prefetch(1, 1); CP_COMMIT();
    __syncthreads();   // q_i staging visible to all warps

    const int arow = lane & 15;
    const int acol = (lane & 16) >> 1;
    const int brow = (lane & 7) | ((lane & 16) >> 1);
    const int bcol = lane & 8;

    float o[8][4];
    #pragma unroll
    for (int t = 0; t < 8; t++)
        #pragma unroll
        for (int e = 0; e < 4; e++) o[t][e] = 0.f;

    for (int c = 0; c < 32; c++) {
        const int buf = c & 1;
        CP_WAIT1();
        __syncthreads();

        #pragma unroll
        for (int half = 0; half < 2; half++) {
            // ---- MMA1: s = qh_i . qh_j^T for 32 j ----
            float s[4][4];
            #pragma unroll
            for (int t = 0; t < 4; t++)
                #pragma unroll
                for (int e = 0; e < 4; e++) s[t][e] = 0.f;

            {
                const uint32_t Asrc = sb + QI_H;
                const uint32_t Bb = sb + QJH(buf);
                #pragma unroll
                for (int ks = 0; ks < 4; ks++) {
                    uint32_t a[4];
                    LDSM4(a[0], a[1], a[2], a[3],
                          Asrc + SWZ((w*16 + arow)*128 + (ks*16 + acol)*2));
                    uint32_t bb[2][4];
                    #pragma unroll
                    for (int ng = 0; ng < 2; ng++)
                        LDSM4(bb[ng][0], bb[ng][1], bb[ng][2], bb[ng][3],
                              Bb + SWZ((half*32 + ng*16 + brow)*128 + (ks*16 + bcol)*2));
                    #pragma unroll
                    for (int nt = 0; nt < 4; nt++)
                        mma_f16(s[nt], a, bb[nt>>1][(nt&1)*2], bb[nt>>1][(nt&1)*2+1]);
                }
            }

            // ---- P = exp(s/8 - c_j) rounded to fp16, packed as A-frags ----
            uint32_t ph01[4], ph23[4];
            #pragma unroll
            for (int nt = 0; nt < 4; nt++) {
                float2 cv = *(const float2*)(smc + CBUF(buf) + (half*32 + nt*8 + (lane&3)*2)*4);
                float p0 = __expf(fmaf(s[nt][0], 0.125f, -cv.x));
                float p1 = __expf(fmaf(s[nt][1], 0.125f, -cv.y));
                float p2 = __expf(fmaf(s[nt][2], 0.125f, -cv.x));
                float p3 = __expf(fmaf(s[nt][3], 0.125f, -cv.y));
                uint16_t h0 = __half_as_ushort(__float2half_rn(p0));
                uint16_t h1 = __half_as_ushort(__float2half_rn(p1));
                uint16_t h2 = __half_as_ushort(__float2half_rn(p2));
                uint16_t h3 = __half_as_ushort(__float2half_rn(p3));
                ph01[nt] = (uint32_t)h0 | ((uint32_t)h1 << 16);
                ph23[nt] = (uint32_t)h2 | ((uint32_t)h3 << 16);
            }

            // ---- MMA2: out += P . qTh over this 32-j half ----
            {
                const uint32_t Bb = sb + QTH(buf);
                #pragma unroll
                for (int ks2 = 0; ks2 < 2; ks2++) {
                    uint32_t a2[4] = { ph01[2*ks2], ph23[2*ks2], ph01[2*ks2+1], ph23[2*ks2+1] };
                    uint32_t bb[4][4];
                    #pragma unroll
                    for (int ng = 0; ng < 4; ng++)
                        LDSM4(bb[ng][0], bb[ng][1], bb[ng][2], bb[ng][3],
                              Bb + SWZ((ng*16 + brow)*128 + (half*32 + ks2*16 + bcol)*2));
                    #pragma unroll
                    for (int nt2 = 0; nt2 < 8; nt2++)
                        mma_f16(o[nt2], a2, bb[nt2>>1][(nt2&1)*2], bb[nt2>>1][(nt2&1)*2+1]);
                }
            }
        }

        __syncthreads();
        if (c + 2 < 32) prefetch(c + 2, buf);
        CP_COMMIT();
    }

    const int g = lane >> 2;
    const int t2 = (lane & 3) * 2;
    #pragma unroll
    for (int nt2 = 0; nt2 < 8; nt2++) {
        int row = i0 + w*16 + g;
        int col = nt2*8 + t2;
        *(float2*)(out + ((size_t)b*TT + row)*DD + col) =
            make_float2(o[nt2][0], o[nt2][1]);
        *(float2*)(out + ((size_t)b*TT + row + 8)*DD + col) =
            make_float2(o[nt2][2], o[nt2][3]);
    }
}

// ---------------------------------------------------------------------------
extern "C" void kernel_launch(void* const* d_in, const int* in_sizes, int n_in,
                              void* d_out, int out_size)
{
    const float* x  = (const float*)d_in[0];
    const float* Wq = (const float*)d_in[1];
    const float* bq = (const float*)d_in[2];
    float* out = (float*)d_out;

    const int smem1 = (64*132 + 64*68 + 64) * 4;

    cudaFuncSetAttribute(k1_proj,  cudaFuncAttributeMaxDynamicSharedMemorySize, smem1);
    cudaFuncSetAttribute(ka_stats, cudaFuncAttributeMaxDynamicSharedMemorySize, KA_SMEM);
    cudaFuncSetAttribute(kb_fused, cudaFuncAttributeMaxDynamicSharedMemorySize, KB_SMEM);

    k1_proj<<<NN/128, 128, smem1>>>(x, Wq, bq);
    ka_stats<<<dim3(136, BB), 256, KA_SMEM>>>();
    k3_logz<<<NN/256, 256>>>();
    kb_fused<<<dim3(TT/128, BB), 256, KB_SMEM>>>(out);
}

// round 12
// speedup vs baseline: 2.2179x; 1.2631x over previous
#include <cuda_runtime.h>
#include <cuda_fp16.h>
#include <cstdint>
#include <cstddef>

#define TT 2048
#define BB 16
#define DD 64
#define EE 512
#define NN (BB*TT)

// ---------------------------------------------------------------------------
// Global scratch  (all MMA operands are fp16 hi-only; softmax self-consistent)
// ---------------------------------------------------------------------------
__device__ uint16_t g_qh[(size_t)NN * DD];       // q hi  (fp16 bits), row-major [N][64]
__device__ uint16_t g_qTh[(size_t)NN * DD];      // q^T hi, [b][64][2048]
__device__ float    g_part[(size_t)NN * 16];     // per-(row, j-tile) exp partial sums
__device__ float    g_c[NN];                     // c = log(rowsumexp)

typedef unsigned long long ull;

// ---------------------------------------------------------------------------
// helpers
// ---------------------------------------------------------------------------
__device__ __forceinline__ uint32_t smem_u32(const void* p) {
    uint32_t a;
    asm("{ .reg .u64 t; cvta.to.shared.u64 t, %1; cvt.u32.u64 %0, t; }" : "=r"(a) : "l"(p));
    return a;
}
#define SWZ(o) ((o) ^ (((o) >> 3) & 0x70))

#define LDSM4(r0,r1,r2,r3,a) \
    asm volatile("ldmatrix.sync.aligned.m8n8.x4.shared.b16 {%0,%1,%2,%3}, [%4];" \
        : "=r"(r0),"=r"(r1),"=r"(r2),"=r"(r3) : "r"(a))

__device__ __forceinline__ void mma_f16(float* d, const uint32_t* a,
                                        uint32_t b0, uint32_t b1) {
    asm volatile("mma.sync.aligned.m16n8k16.row.col.f32.f16.f16.f32 "
        "{%0,%1,%2,%3}, {%4,%5,%6,%7}, {%8,%9}, {%0,%1,%2,%3};"
        : "+f"(d[0]),"+f"(d[1]),"+f"(d[2]),"+f"(d[3])
        : "r"(a[0]),"r"(a[1]),"r"(a[2]),"r"(a[3]), "r"(b0),"r"(b1));
}

#define CPA16(dst, src) \
    asm volatile("cp.async.cg.shared.global [%0], [%1], 16;" :: "r"(dst), "l"(src) : "memory")
#define CP_COMMIT() asm volatile("cp.async.commit_group;" ::: "memory")
#define CP_WAIT1()  asm volatile("cp.async.wait_group 1;" ::: "memory")

// ---------------------------------------------------------------------------
// K1: q = x @ Wq + bq via fp16 HMMA, x 2-split (hi+lo), W hi-only.
// grid 256 (128 rows each), 256 threads (8 warps, m16 each).
// smem: A_h 16K | A_l 16K | Bt 8K | bias 256B ; epilogue reuses A for staging.
// ---------------------------------------------------------------------------
#define K1_AH 0
#define K1_AL 16384
#define K1_BT 32768
#define K1_BS 40960
#define K1_SMEM 41216

__global__ __launch_bounds__(256) void k1_proj(
    const float* __restrict__ x, const float* __restrict__ Wq,
    const float* __restrict__ bq)
{
    extern __shared__ char smc[];
    const uint32_t sb = smem_u32(smc);
    float* bs = (float*)(smc + K1_BS);
    const int tid = threadIdx.x, lane = tid & 31, w = tid >> 5;
    const int r0 = blockIdx.x * 128;
    const int b = r0 >> 11;
    const int t0l = r0 & (TT - 1);

    if (tid < 64) bs[tid] = bq[tid];

    const int arow = lane & 15;
    const int acol = (lane & 16) >> 1;
    const int brow = (lane & 7) | ((lane & 16) >> 1);
    const int bcol = lane & 8;

    float acc[8][4];
    #pragma unroll
    for (int t = 0; t < 8; t++)
        #pragma unroll
        for (int e = 0; e < 4; e++) acc[t][e] = 0.f;

    for (int kc = 0; kc < 8; kc++) {
        __syncthreads();
        // ---- x chunk [128 rows][64 k] fp32 -> fp16 hi/lo swizzled tiles ----
        #pragma unroll
        for (int it = 0; it < 4; it++) {
            int idx = it*256 + tid;
            int r = idx >> 3, kg = idx & 7;
            const float* xp = x + (size_t)(r0 + r)*EE + kc*64 + kg*8;
            float4 v0 = *(const float4*)(xp);
            float4 v1 = *(const float4*)(xp + 4);
            float vv[8] = {v0.x,v0.y,v0.z,v0.w,v1.x,v1.y,v1.z,v1.w};
            uint32_t h[8], l[8];
            #pragma unroll
            for (int q2 = 0; q2 < 8; q2++) {
                __half hh = __float2half_rn(vv[q2]);
                h[q2] = (uint32_t)__half_as_ushort(hh);
                l[q2] = (uint32_t)__half_as_ushort(__float2half_rn(vv[q2] - __half2float(hh)));
            }
            uint4 uh, ul;
            uh.x = h[0]|(h[1]<<16); uh.y = h[2]|(h[3]<<16);
            uh.z = h[4]|(h[5]<<16); uh.w = h[6]|(h[7]<<16);
            ul.x = l[0]|(l[1]<<16); ul.y = l[2]|(l[3]<<16);
            ul.z = l[4]|(l[5]<<16); ul.w = l[6]|(l[7]<<16);
            *(uint4*)(smc + K1_AH + SWZ(r*128 + kg*16)) = uh;
            *(uint4*)(smc + K1_AL + SWZ(r*128 + kg*16)) = ul;
        }
        // ---- W chunk [64 k][64 d] -> transposed fp16 tile Bt [64 d][64 k] ----
        #pragma unroll
        for (int it = 0; it < 2; it++) {
            int idx = it*256 + tid;
            int d = idx >> 3, kg = idx & 7;
            uint32_t h[8];
            #pragma unroll
            for (int k2 = 0; k2 < 8; k2++)
                h[k2] = (uint32_t)__half_as_ushort(__float2half_rn(
                    Wq[(size_t)(kc*64 + kg*8 + k2)*DD + d]));
            uint4 uh;
            uh.x = h[0]|(h[1]<<16); uh.y = h[2]|(h[3]<<16);
            uh.z = h[4]|(h[5]<<16); uh.w = h[6]|(h[7]<<16);
            *(uint4*)(smc + K1_BT + SWZ(d*128 + kg*16)) = uh;
        }
        __syncthreads();
        // ---- MMA: acc += (x_h + x_l) . Wt_h ----
        #pragma unroll
        for (int ks = 0; ks < 4; ks++) {
            uint32_t ah[4], al[4], bbw[4][4];
            LDSM4(ah[0], ah[1], ah[2], ah[3],
                  sb + K1_AH + SWZ((w*16 + arow)*128 + (ks*16 + acol)*2));
            LDSM4(al[0], al[1], al[2], al[3],
                  sb + K1_AL + SWZ((w*16 + arow)*128 + (ks*16 + acol)*2));
            #pragma unroll
            for (int ng = 0; ng < 4; ng++)
                LDSM4(bbw[ng][0], bbw[ng][1], bbw[ng][2], bbw[ng][3],
                      sb + K1_BT + SWZ((ng*16 + brow)*128 + (ks*16 + bcol)*2));
            #pragma unroll
            for (int nt = 0; nt < 8; nt++)
                mma_f16(acc[nt], ah, bbw[nt>>1][(nt&1)*2], bbw[nt>>1][(nt&1)*2+1]);
            #pragma unroll
            for (int nt = 0; nt < 8; nt++)
                mma_f16(acc[nt], al, bbw[nt>>1][(nt&1)*2], bbw[nt>>1][(nt&1)*2+1]);
        }
    }
    __syncthreads();   // MMA reads done; reuse smem for transpose staging

    // ---- epilogue: bias, fp16 round once, write row-major + stage transpose
    uint16_t* st = (uint16_t*)smc;   // [64 d][132 rows]
    const int g = lane >> 2;
    const int c2 = (lane & 3) * 2;
    #pragma unroll
    for (int nt = 0; nt < 8; nt++) {
        int col = nt*8 + c2;
        float b0 = bs[col], b1 = bs[col+1];
        uint32_t h00 = (uint32_t)__half_as_ushort(__float2half_rn(acc[nt][0] + b0));
        uint32_t h01 = (uint32_t)__half_as_ushort(__float2half_rn(acc[nt][1] + b1));
        uint32_t h10 = (uint32_t)__half_as_ushort(__float2half_rn(acc[nt][2] + b0));
        uint32_t h11 = (uint32_t)__half_as_ushort(__float2half_rn(acc[nt][3] + b1));
        int row = w*16 + g;
        *(uint32_t*)(g_qh + (size_t)(r0 + row)*DD + col)     = h00 | (h01 << 16);
        *(uint32_t*)(g_qh + (size_t)(r0 + row + 8)*DD + col) = h10 | (h11 << 16);
        st[col*132 + row]         = (uint16_t)h00;
        st[(col+1)*132 + row]     = (uint16_t)h01;
        st[col*132 + row + 8]     = (uint16_t)h10;
        st[(col+1)*132 + row + 8] = (uint16_t)h11;
    }
    __syncthreads();
    #pragma unroll
    for (int it = 0; it < 4; it++) {
        int idx = it*256 + tid;
        int d = idx >> 4, tg = idx & 15;   // d in [0,64), tg covers 16 groups x 8 rows
        uint32_t u[8];
        #pragma unroll
        for (int t2 = 0; t2 < 8; t2++) u[t2] = (uint32_t)st[d*132 + tg*8 + t2];
        uint4 o;
        o.x = u[0]|(u[1]<<16); o.y = u[2]|(u[3]<<16);
        o.z = u[4]|(u[5]<<16); o.w = u[6]|(u[7]<<16);
        *(uint4*)(g_qTh + ((size_t)b*DD + d)*TT + t0l + tg*8) = o;
    }
}

// ---------------------------------------------------------------------------
// KA: stats only. S̃ = qh_i . qh_j^T /8 (1 fp16 MMA pass, bitwise-consistent
// with KB's recompute); exp partial row & col sums -> g_part.
// grid (136, 16), 256 threads.
// ---------------------------------------------------------------------------
#define KA_SMEM (32768 + 2048 + 1024)

__global__ __launch_bounds__(256) void ka_stats()
{
    extern __shared__ char smc[];
    float* rowpart = (float*)(smc + 32768);            // [4 wn][128 rows]
    float* colpart = (float*)(smc + 32768 + 2048);     // [2 wm][128 cols]
    const uint32_t sb = smem_u32(smc);
    const int tid = threadIdx.x, lane = tid & 31, w = tid >> 5;
    const int b = blockIdx.y;
    int jy = 0, rem = blockIdx.x;
    while (rem >= 16 - jy) { rem -= 16 - jy; jy++; }
    const int ix = jy + rem;
    const int i0 = ix * 128, j0 = jy * 128;

    // 2 operand tiles: A_h (rows i0), B_h (rows j0)
    #pragma unroll
    for (int it = 0; it < 8; it++) {
        int idx = it*256 + tid;
        int tile = idx >> 10;
        int r = (idx >> 3) & 127, ch = idx & 7;
        int grow = (tile == 0) ? (i0 + r) : (j0 + r);
        uint4 v = *(const uint4*)(g_qh + ((size_t)(b*TT + grow))*DD + ch*8);
        *(uint4*)(smc + tile*16384 + SWZ(r*128 + ch*16)) = v;
    }
    __syncthreads();

    const int wm = w >> 2, wn = w & 3;
    const int arow = lane & 15;
    const int acol = (lane & 16) >> 1;
    const int brow = (lane & 7) | ((lane & 16) >> 1);
    const int bcol = lane & 8;

    float d[16][4];
    #pragma unroll
    for (int t = 0; t < 16; t++)
        #pragma unroll
        for (int e = 0; e < 4; e++) d[t][e] = 0.f;

    {
        const uint32_t Ab = sb;
        const uint32_t Bb = sb + 16384;
        #pragma unroll
        for (int ks = 0; ks < 4; ks++) {
            uint32_t a[4][4];
            #pragma unroll
            for (int mt = 0; mt < 4; mt++)
                LDSM4(a[mt][0], a[mt][1], a[mt][2], a[mt][3],
                      Ab + SWZ((wm*64 + mt*16 + arow)*128 + (ks*16 + acol)*2));
            uint32_t bb[2][4];
            #pragma unroll
            for (int ng = 0; ng < 2; ng++)
                LDSM4(bb[ng][0], bb[ng][1], bb[ng][2], bb[ng][3],
                      Bb + SWZ((wn*32 + ng*16 + brow)*128 + (ks*16 + bcol)*2));
            #pragma unroll
            for (int mt = 0; mt < 4; mt++)
                #pragma unroll
                for (int nt = 0; nt < 4; nt++)
                    mma_f16(d[mt*4+nt], a[mt],
                            bb[nt>>1][(nt&1)*2], bb[nt>>1][(nt&1)*2+1]);
        }
    }

    const int r_i = lane >> 2;
    const bool diag = (ix == jy);

    float rp[4][2], cp[4][2];
    #pragma unroll
    for (int t = 0; t < 4; t++) { rp[t][0]=rp[t][1]=0.f; cp[t][0]=cp[t][1]=0.f; }

    #pragma unroll
    for (int mt = 0; mt < 4; mt++) {
        #pragma unroll
        for (int nt = 0; nt < 4; nt++) {
            float e0 = __expf(d[mt*4+nt][0]*0.125f);
            float e1 = __expf(d[mt*4+nt][1]*0.125f);
            float e2 = __expf(d[mt*4+nt][2]*0.125f);
            float e3 = __expf(d[mt*4+nt][3]*0.125f);
            rp[mt][0] += e0 + e1;  rp[mt][1] += e2 + e3;
            cp[nt][0] += e0 + e2;  cp[nt][1] += e1 + e3;
        }
    }
    #pragma unroll
    for (int mt = 0; mt < 4; mt++) {
        float r0 = rp[mt][0], r1 = rp[mt][1];
        r0 += __shfl_xor_sync(0xffffffffu, r0, 1); r0 += __shfl_xor_sync(0xffffffffu, r0, 2);
        r1 += __shfl_xor_sync(0xffffffffu, r1, 1); r1 += __shfl_xor_sync(0xffffffffu, r1, 2);
        if ((lane & 3) == 0) {
            int rl = wm*64 + mt*16 + r_i;
            rowpart[wn*128 + rl]     = r0;
            rowpart[wn*128 + rl + 8] = r1;
        }
    }
    #pragma unroll
    for (int nt = 0; nt < 4; nt++) {
        float c0 = cp[nt][0], c1 = cp[nt][1];
        c0 += __shfl_xor_sync(0xffffffffu, c0, 4); c0 += __shfl_xor_sync(0xffffffffu, c0, 8);
        c0 += __shfl_xor_sync(0xffffffffu, c0, 16);
        c1 += __shfl_xor_sync(0xffffffffu, c1, 4); c1 += __shfl_xor_sync(0xffffffffu, c1, 8);
        c1 += __shfl_xor_sync(0xffffffffu, c1, 16);
        if (lane < 4) {
            int cl = wn*32 + nt*8 + lane*2;
            colpart[wm*128 + cl]     = c0;
            colpart[wm*128 + cl + 1] = c1;
        }
    }
    __syncthreads();

    if (tid < 128) {
        float rs = rowpart[tid] + rowpart[128+tid] + rowpart[256+tid] + rowpart[384+tid];
        g_part[((size_t)(b*TT + i0 + tid))*16 + jy] = rs;
        if (!diag) {
            float cs = colpart[tid] + colpart[128+tid];
            g_part[((size_t)(b*TT + j0 + tid))*16 + ix] = cs;
        }
    }
}

// ---------------------------------------------------------------------------
// K3': c[n] = log( sum of 16 partials )
// ---------------------------------------------------------------------------
__global__ __launch_bounds__(256) void k3_logz()
{
    const int n = blockIdx.x * 256 + threadIdx.x;
    const float* p = g_part + (size_t)n * 16;
    float4 a = *(const float4*)(p);
    float4 b = *(const float4*)(p + 4);
    float4 c = *(const float4*)(p + 8);
    float4 e = *(const float4*)(p + 12);
    float s = a.x + a.y + a.z + a.w;
    s += b.x + b.y + b.z + b.w;
    s += c.x + c.y + c.z + c.w;
    s += e.x + e.y + e.z + e.w;
    g_c[n] = logf(s);
}

// ---------------------------------------------------------------------------
// KB: fused out = P.q; S̃ recomputed (1 fp16 MMA pass, consistent with KA),
// P rounded to fp16 (no split), out += P.qTh (1 MMA pass).
// grid (16 i-tiles of 128, 16 b), 256 threads (8 warps, each m16), 2 CTAs/SM.
// ---------------------------------------------------------------------------
#define KB_STRIDE 16640
#define QJH(buf) ((buf)*KB_STRIDE)
#define QTH(buf) ((buf)*KB_STRIDE + 8192)
#define CBUF(buf) ((buf)*KB_STRIDE + 16384)
#define QI_H (2*KB_STRIDE)
#define KB_SMEM (2*KB_STRIDE + 16384)

__global__ __launch_bounds__(256, 2) void kb_fused(float* __restrict__ out)
{
    extern __shared__ char smc[];
    const uint32_t sb = smem_u32(smc);
    const int tid = threadIdx.x, lane = tid & 31, w = tid >> 5;
    const int i0 = blockIdx.x * 128, b = blockIdx.y;

    const uint16_t* qh  = g_qh  + (size_t)b * TT * DD;
    const uint16_t* qTh = g_qTh + (size_t)b * DD * TT;
    const float*    cb  = g_c + b * TT;

    // --- stage q_i [128][64] hi into resident smem tile ---
    #pragma unroll
    for (int it = 0; it < 4; it++) {
        int idx = it*256 + tid;           // 1024: 128 rows x 8 segs
        int r = idx >> 3, seg = idx & 7;
        *(uint4*)(smc + QI_H + SWZ(r*128 + seg*16)) =
            *(const uint4*)(qh + (size_t)(i0 + r)*DD + seg*8);
    }

    auto prefetch = [&](int c, int buf) {
        const int j0c = c * 64;
        #pragma unroll
        for (int k2 = 0; k2 < 2; k2++) {
            int idx = k2*256 + tid;       // 512: 64 rows x 8 segs
            int r = idx >> 3, seg = idx & 7;
            CPA16(sb + QJH(buf) + SWZ(r*128 + seg*16),
                  (const void*)(qh + (size_t)(j0c + r)*DD + seg*8));
            CPA16(sb + QTH(buf) + SWZ(r*128 + seg*16),
                  (const void*)(qTh + (size_t)r*TT + j0c + seg*8));
        }
        if (tid < 16)
            CPA16(sb + CBUF(buf) + tid*16, (const void*)(cb + j0c + tid*4));
    };

    prefetch(0, 0); CP_COMMIT();
    prefetch(1, 1); CP_COMMIT();
    __syncthreads();   // q_i staging visible to all warps

    const int arow = lane & 15;
    const int acol = (lane & 16) >> 1;
    const int brow = (lane & 7) | ((lane & 16) >> 1);
    const int bcol = lane & 8;

    float o[8][4];
    #pragma unroll
    for (int t = 0; t < 8; t++)
        #pragma unroll
        for (int e = 0; e < 4; e++) o[t][e] = 0.f;

    for (int c = 0; c < 32; c++) {
        const int buf = c & 1;
        CP_WAIT1();
        __syncthreads();

        #pragma unroll
        for (int half = 0; half < 2; half++) {
            // ---- MMA1: s = qh_i . qh_j^T for 32 j ----
            float s[4][4];
            #pragma unroll
            for (int t = 0; t < 4; t++)
                #pragma unroll
                for (int e = 0; e < 4; e++) s[t][e] = 0.f;

            {
                const uint32_t Asrc = sb + QI_H;
                const uint32_t Bb = sb + QJH(buf);
                #pragma unroll
                for (int ks = 0; ks < 4; ks++) {
                    uint32_t a[4];
                    LDSM4(a[0], a[1], a[2], a[3],
                          Asrc + SWZ((w*16 + arow)*128 + (ks*16 + acol)*2));
                    uint32_t bb[2][4];
                    #pragma unroll
                    for (int ng = 0; ng < 2; ng++)
                        LDSM4(bb[ng][0], bb[ng][1], bb[ng][2], bb[ng][3],
                              Bb + SWZ((half*32 + ng*16 + brow)*128 + (ks*16 + bcol)*2));
                    #pragma unroll
                    for (int nt = 0; nt < 4; nt++)
                        mma_f16(s[nt], a, bb[nt>>1][(nt&1)*2], bb[nt>>1][(nt&1)*2+1]);
                }
            }

            // ---- P = exp(s/8 - c_j) rounded to fp16, packed as A-frags ----
            uint32_t ph01[4], ph23[4];
            #pragma unroll
            for (int nt = 0; nt < 4; nt++) {
                float2 cv = *(const float2*)(smc + CBUF(buf) + (half*32 + nt*8 + (lane&3)*2)*4);
                float p0 = __expf(fmaf(s[nt][0], 0.125f, -cv.x));
                float p1 = __expf(fmaf(s[nt][1], 0.125f, -cv.y));
                float p2 = __expf(fmaf(s[nt][2], 0.125f, -cv.x));
                float p3 = __expf(fmaf(s[nt][3], 0.125f, -cv.y));
                uint16_t h0 = __half_as_ushort(__float2half_rn(p0));
                uint16_t h1 = __half_as_ushort(__float2half_rn(p1));
                uint16_t h2 = __half_as_ushort(__float2half_rn(p2));
                uint16_t h3 = __half_as_ushort(__float2half_rn(p3));
                ph01[nt] = (uint32_t)h0 | ((uint32_t)h1 << 16);
                ph23[nt] = (uint32_t)h2 | ((uint32_t)h3 << 16);
            }

            // ---- MMA2: out += P . qTh over this 32-j half ----
            {
                const uint32_t Bb = sb + QTH(buf);
                #pragma unroll
                for (int ks2 = 0; ks2 < 2; ks2++) {
                    uint32_t a2[4] = { ph01[2*ks2], ph23[2*ks2], ph01[2*ks2+1], ph23[2*ks2+1] };
                    uint32_t bb[4][4];
                    #pragma unroll
                    for (int ng = 0; ng < 4; ng++)
                        LDSM4(bb[ng][0], bb[ng][1], bb[ng][2], bb[ng][3],
                              Bb + SWZ((ng*16 + brow)*128 + (half*32 + ks2*16 + bcol)*2));
                    #pragma unroll
                    for (int nt2 = 0; nt2 < 8; nt2++)
                        mma_f16(o[nt2], a2, bb[nt2>>1][(nt2&1)*2], bb[nt2>>1][(nt2&1)*2+1]);
                }
            }
        }

        __syncthreads();
        if (c + 2 < 32) prefetch(c + 2, buf);
        CP_COMMIT();
    }

    const int g = lane >> 2;
    const int t2 = (lane & 3) * 2;
    #pragma unroll
    for (int nt2 = 0; nt2 < 8; nt2++) {
        int row = i0 + w*16 + g;
        int col = nt2*8 + t2;
        *(float2*)(out + ((size_t)b*TT + row)*DD + col) =
            make_float2(o[nt2][0], o[nt2][1]);
        *(float2*)(out + ((size_t)b*TT + row + 8)*DD + col) =
            make_float2(o[nt2][2], o[nt2][3]);
    }
}

// ---------------------------------------------------------------------------
extern "C" void kernel_launch(void* const* d_in, const int* in_sizes, int n_in,
                              void* d_out, int out_size)
{
    const float* x  = (const float*)d_in[0];
    const float* Wq = (const float*)d_in[1];
    const float* bq = (const float*)d_in[2];
    float* out = (float*)d_out;

    cudaFuncSetAttribute(k1_proj,  cudaFuncAttributeMaxDynamicSharedMemorySize, K1_SMEM);
    cudaFuncSetAttribute(ka_stats, cudaFuncAttributeMaxDynamicSharedMemorySize, KA_SMEM);
    cudaFuncSetAttribute(kb_fused, cudaFuncAttributeMaxDynamicSharedMemorySize, KB_SMEM);

    k1_proj<<<NN/128, 256, K1_SMEM>>>(x, Wq, bq);
    ka_stats<<<dim3(136, BB), 256, KA_SMEM>>>();
    k3_logz<<<NN/256, 256>>>();
    kb_fused<<<dim3(TT/128, BB), 256, KB_SMEM>>>(out);
}

// round 13
// speedup vs baseline: 2.3804x; 1.0733x over previous
#include <cuda_runtime.h>
#include <cuda_fp16.h>
#include <cstdint>
#include <cstddef>

#define TT 2048
#define BB 16
#define DD 64
#define EE 512
#define NN (BB*TT)

// ---------------------------------------------------------------------------
// Global scratch  (all MMA operands are fp16 hi-only; softmax self-consistent)
// ---------------------------------------------------------------------------
__device__ uint16_t g_qh[(size_t)NN * DD];       // q hi  (fp16 bits), row-major [N][64]
__device__ uint16_t g_qTh[(size_t)NN * DD];      // q^T hi, [b][64][2048]
__device__ float    g_part[(size_t)NN * 16];     // per-(row, j-tile) exp partial sums
__device__ float    g_c[NN];                     // c = log(rowsumexp)

typedef unsigned long long ull;

// ---------------------------------------------------------------------------
// helpers
// ---------------------------------------------------------------------------
__device__ __forceinline__ uint32_t smem_u32(const void* p) {
    uint32_t a;
    asm("{ .reg .u64 t; cvta.to.shared.u64 t, %1; cvt.u32.u64 %0, t; }" : "=r"(a) : "l"(p));
    return a;
}
#define SWZ(o) ((o) ^ (((o) >> 3) & 0x70))

#define LDSM4(r0,r1,r2,r3,a) \
    asm volatile("ldmatrix.sync.aligned.m8n8.x4.shared.b16 {%0,%1,%2,%3}, [%4];" \
        : "=r"(r0),"=r"(r1),"=r"(r2),"=r"(r3) : "r"(a))

__device__ __forceinline__ void mma_f16(float* d, const uint32_t* a,
                                        uint32_t b0, uint32_t b1) {
    asm volatile("mma.sync.aligned.m16n8k16.row.col.f32.f16.f16.f32 "
        "{%0,%1,%2,%3}, {%4,%5,%6,%7}, {%8,%9}, {%0,%1,%2,%3};"
        : "+f"(d[0]),"+f"(d[1]),"+f"(d[2]),"+f"(d[3])
        : "r"(a[0]),"r"(a[1]),"r"(a[2]),"r"(a[3]), "r"(b0),"r"(b1));
}

#define CPA16(dst, src) \
    asm volatile("cp.async.cg.shared.global [%0], [%1], 16;" :: "r"(dst), "l"(src) : "memory")
#define CP_COMMIT() asm volatile("cp.async.commit_group;" ::: "memory")
#define CP_WAIT1()  asm volatile("cp.async.wait_group 1;" ::: "memory")

// ---------------------------------------------------------------------------
// K1: q = x @ Wq + bq via fp16 HMMA, x 2-split (hi+lo), W hi-only.
// grid 256 (128 rows each), 256 threads (8 warps, m16 each).
// ---------------------------------------------------------------------------
#define K1_AH 0
#define K1_AL 16384
#define K1_BT 32768
#define K1_BS 40960
#define K1_SMEM 41216

__global__ __launch_bounds__(256) void k1_proj(
    const float* __restrict__ x, const float* __restrict__ Wq,
    const float* __restrict__ bq)
{
    extern __shared__ char smc[];
    const uint32_t sb = smem_u32(smc);
    float* bs = (float*)(smc + K1_BS);
    const int tid = threadIdx.x, lane = tid & 31, w = tid >> 5;
    const int r0 = blockIdx.x * 128;
    const int b = r0 >> 11;
    const int t0l = r0 & (TT - 1);

    if (tid < 64) bs[tid] = bq[tid];

    const int arow = lane & 15;
    const int acol = (lane & 16) >> 1;
    const int brow = (lane & 7) | ((lane & 16) >> 1);
    const int bcol = lane & 8;

    float acc[8][4];
    #pragma unroll
    for (int t = 0; t < 8; t++)
        #pragma unroll
        for (int e = 0; e < 4; e++) acc[t][e] = 0.f;

    for (int kc = 0; kc < 8; kc++) {
        __syncthreads();
        #pragma unroll
        for (int it = 0; it < 4; it++) {
            int idx = it*256 + tid;
            int r = idx >> 3, kg = idx & 7;
            const float* xp = x + (size_t)(r0 + r)*EE + kc*64 + kg*8;
            float4 v0 = *(const float4*)(xp);
            float4 v1 = *(const float4*)(xp + 4);
            float vv[8] = {v0.x,v0.y,v0.z,v0.w,v1.x,v1.y,v1.z,v1.w};
            uint32_t h[8], l[8];
            #pragma unroll
            for (int q2 = 0; q2 < 8; q2++) {
                __half hh = __float2half_rn(vv[q2]);
                h[q2] = (uint32_t)__half_as_ushort(hh);
                l[q2] = (uint32_t)__half_as_ushort(__float2half_rn(vv[q2] - __half2float(hh)));
            }
            uint4 uh, ul;
            uh.x = h[0]|(h[1]<<16); uh.y = h[2]|(h[3]<<16);
            uh.z = h[4]|(h[5]<<16); uh.w = h[6]|(h[7]<<16);
            ul.x = l[0]|(l[1]<<16); ul.y = l[2]|(l[3]<<16);
            ul.z = l[4]|(l[5]<<16); ul.w = l[6]|(l[7]<<16);
            *(uint4*)(smc + K1_AH + SWZ(r*128 + kg*16)) = uh;
            *(uint4*)(smc + K1_AL + SWZ(r*128 + kg*16)) = ul;
        }
        #pragma unroll
        for (int it = 0; it < 2; it++) {
            int idx = it*256 + tid;
            int d = idx >> 3, kg = idx & 7;
            uint32_t h[8];
            #pragma unroll
            for (int k2 = 0; k2 < 8; k2++)
                h[k2] = (uint32_t)__half_as_ushort(__float2half_rn(
                    Wq[(size_t)(kc*64 + kg*8 + k2)*DD + d]));
            uint4 uh;
            uh.x = h[0]|(h[1]<<16); uh.y = h[2]|(h[3]<<16);
            uh.z = h[4]|(h[5]<<16); uh.w = h[6]|(h[7]<<16);
            *(uint4*)(smc + K1_BT + SWZ(d*128 + kg*16)) = uh;
        }
        __syncthreads();
        #pragma unroll
        for (int ks = 0; ks < 4; ks++) {
            uint32_t ah[4], al[4], bbw[4][4];
            LDSM4(ah[0], ah[1], ah[2], ah[3],
                  sb + K1_AH + SWZ((w*16 + arow)*128 + (ks*16 + acol)*2));
            LDSM4(al[0], al[1], al[2], al[3],
                  sb + K1_AL + SWZ((w*16 + arow)*128 + (ks*16 + acol)*2));
            #pragma unroll
            for (int ng = 0; ng < 4; ng++)
                LDSM4(bbw[ng][0], bbw[ng][1], bbw[ng][2], bbw[ng][3],
                      sb + K1_BT + SWZ((ng*16 + brow)*128 + (ks*16 + bcol)*2));
            #pragma unroll
            for (int nt = 0; nt < 8; nt++)
                mma_f16(acc[nt], ah, bbw[nt>>1][(nt&1)*2], bbw[nt>>1][(nt&1)*2+1]);
            #pragma unroll
            for (int nt = 0; nt < 8; nt++)
                mma_f16(acc[nt], al, bbw[nt>>1][(nt&1)*2], bbw[nt>>1][(nt&1)*2+1]);
        }
    }
    __syncthreads();

    uint16_t* st = (uint16_t*)smc;   // [64 d][132 rows]
    const int g = lane >> 2;
    const int c2 = (lane & 3) * 2;
    #pragma unroll
    for (int nt = 0; nt < 8; nt++) {
        int col = nt*8 + c2;
        float b0 = bs[col], b1 = bs[col+1];
        uint32_t h00 = (uint32_t)__half_as_ushort(__float2half_rn(acc[nt][0] + b0));
        uint32_t h01 = (uint32_t)__half_as_ushort(__float2half_rn(acc[nt][1] + b1));
        uint32_t h10 = (uint32_t)__half_as_ushort(__float2half_rn(acc[nt][2] + b0));
        uint32_t h11 = (uint32_t)__half_as_ushort(__float2half_rn(acc[nt][3] + b1));
        int row = w*16 + g;
        *(uint32_t*)(g_qh + (size_t)(r0 + row)*DD + col)     = h00 | (h01 << 16);
        *(uint32_t*)(g_qh + (size_t)(r0 + row + 8)*DD + col) = h10 | (h11 << 16);
        st[col*132 + row]         = (uint16_t)h00;
        st[(col+1)*132 + row]     = (uint16_t)h01;
        st[col*132 + row + 8]     = (uint16_t)h10;
        st[(col+1)*132 + row + 8] = (uint16_t)h11;
    }
    __syncthreads();
    #pragma unroll
    for (int it = 0; it < 4; it++) {
        int idx = it*256 + tid;
        int d = idx >> 4, tg = idx & 15;
        uint32_t u[8];
        #pragma unroll
        for (int t2 = 0; t2 < 8; t2++) u[t2] = (uint32_t)st[d*132 + tg*8 + t2];
        uint4 o;
        o.x = u[0]|(u[1]<<16); o.y = u[2]|(u[3]<<16);
        o.z = u[4]|(u[5]<<16); o.w = u[6]|(u[7]<<16);
        *(uint4*)(g_qTh + ((size_t)b*DD + d)*TT + t0l + tg*8) = o;
    }
}

// ---------------------------------------------------------------------------
// KA: stats only. S̃ = qh_i . qh_j^T /8 (1 fp16 MMA pass, bitwise-consistent
// with KB's recompute); exp partial row & col sums -> g_part.
// ---------------------------------------------------------------------------
#define KA_SMEM (32768 + 2048 + 1024)

__global__ __launch_bounds__(256) void ka_stats()
{
    extern __shared__ char smc[];
    float* rowpart = (float*)(smc + 32768);
    float* colpart = (float*)(smc + 32768 + 2048);
    const uint32_t sb = smem_u32(smc);
    const int tid = threadIdx.x, lane = tid & 31, w = tid >> 5;
    const int b = blockIdx.y;
    int jy = 0, rem = blockIdx.x;
    while (rem >= 16 - jy) { rem -= 16 - jy; jy++; }
    const int ix = jy + rem;
    const int i0 = ix * 128, j0 = jy * 128;

    #pragma unroll
    for (int it = 0; it < 8; it++) {
        int idx = it*256 + tid;
        int tile = idx >> 10;
        int r = (idx >> 3) & 127, ch = idx & 7;
        int grow = (tile == 0) ? (i0 + r) : (j0 + r);
        uint4 v = *(const uint4*)(g_qh + ((size_t)(b*TT + grow))*DD + ch*8);
        *(uint4*)(smc + tile*16384 + SWZ(r*128 + ch*16)) = v;
    }
    __syncthreads();

    const int wm = w >> 2, wn = w & 3;
    const int arow = lane & 15;
    const int acol = (lane & 16) >> 1;
    const int brow = (lane & 7) | ((lane & 16) >> 1);
    const int bcol = lane & 8;

    float d[16][4];
    #pragma unroll
    for (int t = 0; t < 16; t++)
        #pragma unroll
        for (int e = 0; e < 4; e++) d[t][e] = 0.f;

    {
        const uint32_t Ab = sb;
        const uint32_t Bb = sb + 16384;
        #pragma unroll
        for (int ks = 0; ks < 4; ks++) {
            uint32_t a[4][4];
            #pragma unroll
            for (int mt = 0; mt < 4; mt++)
                LDSM4(a[mt][0], a[mt][1], a[mt][2], a[mt][3],
                      Ab + SWZ((wm*64 + mt*16 + arow)*128 + (ks*16 + acol)*2));
            uint32_t bb[2][4];
            #pragma unroll
            for (int ng = 0; ng < 2; ng++)
                LDSM4(bb[ng][0], bb[ng][1], bb[ng][2], bb[ng][3],
                      Bb + SWZ((wn*32 + ng*16 + brow)*128 + (ks*16 + bcol)*2));
            #pragma unroll
            for (int mt = 0; mt < 4; mt++)
                #pragma unroll
                for (int nt = 0; nt < 4; nt++)
                    mma_f16(d[mt*4+nt], a[mt],
                            bb[nt>>1][(nt&1)*2], bb[nt>>1][(nt&1)*2+1]);
        }
    }

    const int r_i = lane >> 2;
    const bool diag = (ix == jy);

    float rp[4][2], cp[4][2];
    #pragma unroll
    for (int t = 0; t < 4; t++) { rp[t][0]=rp[t][1]=0.f; cp[t][0]=cp[t][1]=0.f; }

    #pragma unroll
    for (int mt = 0; mt < 4; mt++) {
        #pragma unroll
        for (int nt = 0; nt < 4; nt++) {
            float e0 = __expf(d[mt*4+nt][0]*0.125f);
            float e1 = __expf(d[mt*4+nt][1]*0.125f);
            float e2 = __expf(d[mt*4+nt][2]*0.125f);
            float e3 = __expf(d[mt*4+nt][3]*0.125f);
            rp[mt][0] += e0 + e1;  rp[mt][1] += e2 + e3;
            cp[nt][0] += e0 + e2;  cp[nt][1] += e1 + e3;
        }
    }
    #pragma unroll
    for (int mt = 0; mt < 4; mt++) {
        float r0 = rp[mt][0], r1 = rp[mt][1];
        r0 += __shfl_xor_sync(0xffffffffu, r0, 1); r0 += __shfl_xor_sync(0xffffffffu, r0, 2);
        r1 += __shfl_xor_sync(0xffffffffu, r1, 1); r1 += __shfl_xor_sync(0xffffffffu, r1, 2);
        if ((lane & 3) == 0) {
            int rl = wm*64 + mt*16 + r_i;
            rowpart[wn*128 + rl]     = r0;
            rowpart[wn*128 + rl + 8] = r1;
        }
    }
    #pragma unroll
    for (int nt = 0; nt < 4; nt++) {
        float c0 = cp[nt][0], c1 = cp[nt][1];
        c0 += __shfl_xor_sync(0xffffffffu, c0, 4); c0 += __shfl_xor_sync(0xffffffffu, c0, 8);
        c0 += __shfl_xor_sync(0xffffffffu, c0, 16);
        c1 += __shfl_xor_sync(0xffffffffu, c1, 4); c1 += __shfl_xor_sync(0xffffffffu, c1, 8);
        c1 += __shfl_xor_sync(0xffffffffu, c1, 16);
        if (lane < 4) {
            int cl = wn*32 + nt*8 + lane*2;
            colpart[wm*128 + cl]     = c0;
            colpart[wm*128 + cl + 1] = c1;
        }
    }
    __syncthreads();

    if (tid < 128) {
        float rs = rowpart[tid] + rowpart[128+tid] + rowpart[256+tid] + rowpart[384+tid];
        g_part[((size_t)(b*TT + i0 + tid))*16 + jy] = rs;
        if (!diag) {
            float cs = colpart[tid] + colpart[128+tid];
            g_part[((size_t)(b*TT + j0 + tid))*16 + ix] = cs;
        }
    }
}

// ---------------------------------------------------------------------------
// K3': c[n] = log( sum of 16 partials )
// ---------------------------------------------------------------------------
__global__ __launch_bounds__(256) void k3_logz()
{
    const int n = blockIdx.x * 256 + threadIdx.x;
    const float* p = g_part + (size_t)n * 16;
    float4 a = *(const float4*)(p);
    float4 b = *(const float4*)(p + 4);
    float4 c = *(const float4*)(p + 8);
    float4 e = *(const float4*)(p + 12);
    float s = a.x + a.y + a.z + a.w;
    s += b.x + b.y + b.z + b.w;
    s += c.x + c.y + c.z + c.w;
    s += e.x + e.y + e.z + e.w;
    g_c[n] = logf(s);
}

// ---------------------------------------------------------------------------
// KB: fused out = P.q; S̃ recomputed (consistent with KA), P fp16.
// i-tile 256, 8 warps x m32, q_i A-fragments cached in registers.
// grid (8 i-tiles, 16 b) = 128 CTAs, 256 threads, 1 CTA/SM.
// ---------------------------------------------------------------------------
#define KB_STRIDE 16640
#define QJH(buf) ((buf)*KB_STRIDE)
#define QTH(buf) ((buf)*KB_STRIDE + 8192)
#define CBUF(buf) ((buf)*KB_STRIDE + 16384)
#define QI_H (2*KB_STRIDE)
#define KB_SMEM (2*KB_STRIDE + 32768)

__global__ __launch_bounds__(256, 1) void kb_fused(float* __restrict__ out)
{
    extern __shared__ char smc[];
    const uint32_t sb = smem_u32(smc);
    const int tid = threadIdx.x, lane = tid & 31, w = tid >> 5;
    const int i0 = blockIdx.x * 256, b = blockIdx.y;

    const uint16_t* qh  = g_qh  + (size_t)b * TT * DD;
    const uint16_t* qTh = g_qTh + (size_t)b * DD * TT;
    const float*    cb  = g_c + b * TT;

    // --- stage q_i [256][64] into resident smem tile ---
    #pragma unroll
    for (int it = 0; it < 8; it++) {
        int idx = it*256 + tid;           // 2048: 256 rows x 8 segs
        int r = idx >> 3, seg = idx & 7;
        *(uint4*)(smc + QI_H + SWZ(r*128 + seg*16)) =
            *(const uint4*)(qh + (size_t)(i0 + r)*DD + seg*8);
    }

    auto prefetch = [&](int c, int buf) {
        const int j0c = c * 64;
        #pragma unroll
        for (int k2 = 0; k2 < 2; k2++) {
            int idx = k2*256 + tid;       // 512: 64 rows x 8 segs
            int r = idx >> 3, seg = idx & 7;
            CPA16(sb + QJH(buf) + SWZ(r*128 + seg*16),
                  (const void*)(qh + (size_t)(j0c + r)*DD + seg*8));
            CPA16(sb + QTH(buf) + SWZ(r*128 + seg*16),
                  (const void*)(qTh + (size_t)r*TT + j0c + seg*8));
        }
        if (tid < 16)
            CPA16(sb + CBUF(buf) + tid*16, (const void*)(cb + j0c + tid*4));
    };

    prefetch(0, 0); CP_COMMIT();
    prefetch(1, 1); CP_COMMIT();
    __syncthreads();   // q_i staging visible to all warps

    const int arow = lane & 15;
    const int acol = (lane & 16) >> 1;
    const int brow = (lane & 7) | ((lane & 16) >> 1);
    const int bcol = lane & 8;

    // --- cache q_i A-fragments: 2 m-blocks x 4 ks ---
    uint32_t aq[2][4][4];
    #pragma unroll
    for (int mt = 0; mt < 2; mt++)
        #pragma unroll
        for (int ks = 0; ks < 4; ks++)
            LDSM4(aq[mt][ks][0], aq[mt][ks][1], aq[mt][ks][2], aq[mt][ks][3],
                  sb + QI_H + SWZ((w*32 + mt*16 + arow)*128 + (ks*16 + acol)*2));

    float o[2][8][4];
    #pragma unroll
    for (int mt = 0; mt < 2; mt++)
        #pragma unroll
        for (int t = 0; t < 8; t++)
            #pragma unroll
            for (int e = 0; e < 4; e++) o[mt][t][e] = 0.f;

    for (int c = 0; c < 32; c++) {
        const int buf = c & 1;
        CP_WAIT1();
        __syncthreads();

        #pragma unroll
        for (int half = 0; half < 2; half++) {
            // ---- MMA1: s = qh_i . qh_j^T for 32 j, m32 ----
            float s[2][4][4];
            #pragma unroll
            for (int mt = 0; mt < 2; mt++)
                #pragma unroll
                for (int t = 0; t < 4; t++)
                    #pragma unroll
                    for (int e = 0; e < 4; e++) s[mt][t][e] = 0.f;

            #pragma unroll
            for (int ks = 0; ks < 4; ks++) {
                uint32_t bb[2][4];
                #pragma unroll
                for (int ng = 0; ng < 2; ng++)
                    LDSM4(bb[ng][0], bb[ng][1], bb[ng][2], bb[ng][3],
                          sb + QJH(buf) + SWZ((half*32 + ng*16 + brow)*128 + (ks*16 + bcol)*2));
                #pragma unroll
                for (int mt = 0; mt < 2; mt++)
                    #pragma unroll
                    for (int nt = 0; nt < 4; nt++)
                        mma_f16(s[mt][nt], aq[mt][ks],
                                bb[nt>>1][(nt&1)*2], bb[nt>>1][(nt&1)*2+1]);
            }

            // ---- P = exp(s/8 - c_j) rounded to fp16, packed as A-frags ----
            uint32_t ph01[2][4], ph23[2][4];
            #pragma unroll
            for (int mt = 0; mt < 2; mt++) {
                #pragma unroll
                for (int nt = 0; nt < 4; nt++) {
                    float2 cv = *(const float2*)(smc + CBUF(buf) + (half*32 + nt*8 + (lane&3)*2)*4);
                    float p0 = __expf(fmaf(s[mt][nt][0], 0.125f, -cv.x));
                    float p1 = __expf(fmaf(s[mt][nt][1], 0.125f, -cv.y));
                    float p2 = __expf(fmaf(s[mt][nt][2], 0.125f, -cv.x));
                    float p3 = __expf(fmaf(s[mt][nt][3], 0.125f, -cv.y));
                    uint16_t h0 = __half_as_ushort(__float2half_rn(p0));
                    uint16_t h1 = __half_as_ushort(__float2half_rn(p1));
                    uint16_t h2 = __half_as_ushort(__float2half_rn(p2));
                    uint16_t h3 = __half_as_ushort(__float2half_rn(p3));
                    ph01[mt][nt] = (uint32_t)h0 | ((uint32_t)h1 << 16);
                    ph23[mt][nt] = (uint32_t)h2 | ((uint32_t)h3 << 16);
                }
            }

            // ---- MMA2: out += P . qTh over this 32-j half ----
            #pragma unroll
            for (int ks2 = 0; ks2 < 2; ks2++) {
                uint32_t bb[4][4];
                #pragma unroll
                for (int ng = 0; ng < 4; ng++)
                    LDSM4(bb[ng][0], bb[ng][1], bb[ng][2], bb[ng][3],
                          sb + QTH(buf) + SWZ((ng*16 + brow)*128 + (half*32 + ks2*16 + bcol)*2));
                #pragma unroll
                for (int mt = 0; mt < 2; mt++) {
                    uint32_t a2[4] = { ph01[mt][2*ks2], ph23[mt][2*ks2],
                                       ph01[mt][2*ks2+1], ph23[mt][2*ks2+1] };
                    #pragma unroll
                    for (int nt2 = 0; nt2 < 8; nt2++)
                        mma_f16(o[mt][nt2], a2,
                                bb[nt2>>1][(nt2&1)*2], bb[nt2>>1][(nt2&1)*2+1]);
                }
            }
        }

        __syncthreads();
        if (c + 2 < 32) prefetch(c + 2, buf);
        CP_COMMIT();
    }

    const int g = lane >> 2;
    const int t2 = (lane & 3) * 2;
    #pragma unroll
    for (int mt = 0; mt < 2; mt++) {
        #pragma unroll
        for (int nt2 = 0; nt2 < 8; nt2++) {
            int row = i0 + w*32 + mt*16 + g;
            int col = nt2*8 + t2;
            *(float2*)(out + ((size_t)b*TT + row)*DD + col) =
                make_float2(o[mt][nt2][0], o[mt][nt2][1]);
            *(float2*)(out + ((size_t)b*TT + row + 8)*DD + col) =
                make_float2(o[mt][nt2][2], o[mt][nt2][3]);
        }
    }
}

// ---------------------------------------------------------------------------
extern "C" void kernel_launch(void* const* d_in, const int* in_sizes, int n_in,
                              void* d_out, int out_size)
{
    const float* x  = (const float*)d_in[0];
    const float* Wq = (const float*)d_in[1];
    const float* bq = (const float*)d_in[2];
    float* out = (float*)d_out;

    cudaFuncSetAttribute(k1_proj,  cudaFuncAttributeMaxDynamicSharedMemorySize, K1_SMEM);
    cudaFuncSetAttribute(ka_stats, cudaFuncAttributeMaxDynamicSharedMemorySize, KA_SMEM);
    cudaFuncSetAttribute(kb_fused, cudaFuncAttributeMaxDynamicSharedMemorySize, KB_SMEM);

    k1_proj<<<NN/128, 256, K1_SMEM>>>(x, Wq, bq);
    ka_stats<<<dim3(136, BB), 256, KA_SMEM>>>();
    k3_logz<<<NN/256, 256>>>();
    kb_fused<<<dim3(TT/256, BB), 256, KB_SMEM>>>(out);
}

// round 15
// speedup vs baseline: 2.3955x; 1.0063x over previous
#include <cuda_runtime.h>
#include <cuda_fp16.h>
#include <cstdint>
#include <cstddef>

#define TT 2048
#define BB 16
#define DD 64
#define EE 512
#define NN (BB*TT)

#define LOG2E8 0.18033688011112042f   // 0.125 * log2(e)

// ---------------------------------------------------------------------------
// Global scratch  (all MMA operands are fp16 hi-only; softmax self-consistent)
// ---------------------------------------------------------------------------
__device__ uint16_t g_qh[(size_t)NN * DD];       // q hi  (fp16), row-major [N][64]
__device__ uint16_t g_qTh[(size_t)NN * DD];      // q^T hi, [b][64][2048]
__device__ uint16_t g_wt[(size_t)DD * EE];       // Wq^T fp16 [64 d][512 k]
__device__ float    g_part[(size_t)NN * 16];     // per-(row, j-tile) exp partial sums
__device__ float    g_c[NN];                     // c2 = log2(rowsumexp)

typedef unsigned long long ull;

// ---------------------------------------------------------------------------
// helpers
// ---------------------------------------------------------------------------
__device__ __forceinline__ uint32_t smem_u32(const void* p) {
    uint32_t a;
    asm("{ .reg .u64 t; cvta.to.shared.u64 t, %1; cvt.u32.u64 %0, t; }" : "=r"(a) : "l"(p));
    return a;
}
#define SWZ(o) ((o) ^ (((o) >> 3) & 0x70))

#define LDSM4(r0,r1,r2,r3,a) \
    asm volatile("ldmatrix.sync.aligned.m8n8.x4.shared.b16 {%0,%1,%2,%3}, [%4];" \
        : "=r"(r0),"=r"(r1),"=r"(r2),"=r"(r3) : "r"(a))

__device__ __forceinline__ void mma_f16(float* d, const uint32_t* a,
                                        uint32_t b0, uint32_t b1) {
    asm volatile("mma.sync.aligned.m16n8k16.row.col.f32.f16.f16.f32 "
        "{%0,%1,%2,%3}, {%4,%5,%6,%7}, {%8,%9}, {%0,%1,%2,%3};"
        : "+f"(d[0]),"+f"(d[1]),"+f"(d[2]),"+f"(d[3])
        : "r"(a[0]),"r"(a[1]),"r"(a[2]),"r"(a[3]), "r"(b0),"r"(b1));
}

#define CPA16(dst, src) \
    asm volatile("cp.async.cg.shared.global [%0], [%1], 16;" :: "r"(dst), "l"(src) : "memory")
#define CP_COMMIT() asm volatile("cp.async.commit_group;" ::: "memory")
#define CP_WAIT1()  asm volatile("cp.async.wait_group 1;" ::: "memory")

// ---------------------------------------------------------------------------
// k0: one-time Wq [512][64] fp32 -> g_wt [64][512] fp16 (smem transpose)
// grid 8 (64 k-rows each), 256 threads
// ---------------------------------------------------------------------------
__global__ __launch_bounds__(256) void k0_wcvt(const float* __restrict__ Wq)
{
    __shared__ float ws[64][68];
    const int tid = threadIdx.x;
    const int k0 = blockIdx.x * 64;
    #pragma unroll
    for (int it = 0; it < 4; it++) {
        int idx = it*256 + tid;
        int r = idx >> 4, c4 = idx & 15;
        float4 v = *(const float4*)(Wq + (size_t)(k0 + r)*DD + c4*4);
        ws[r][c4*4+0] = v.x; ws[r][c4*4+1] = v.y;
        ws[r][c4*4+2] = v.z; ws[r][c4*4+3] = v.w;
    }
    __syncthreads();
    #pragma unroll
    for (int it = 0; it < 2; it++) {
        int idx = it*256 + tid;
        int d = idx >> 3, kg = idx & 7;
        uint32_t h[8];
        #pragma unroll
        for (int j = 0; j < 8; j++)
            h[j] = (uint32_t)__half_as_ushort(__float2half_rn(ws[kg*8 + j][d]));
        uint4 o;
        o.x = h[0]|(h[1]<<16); o.y = h[2]|(h[3]<<16);
        o.z = h[4]|(h[5]<<16); o.w = h[6]|(h[7]<<16);
        *(uint4*)(g_wt + (size_t)d*EE + k0 + kg*8) = o;
    }
}

// ---------------------------------------------------------------------------
// K1: q = x @ Wq + bq via fp16 HMMA, x 2-split (hi+lo), W from g_wt (fp16).
// grid 256 (128 rows each), 256 threads (8 warps, m16 each).
// ---------------------------------------------------------------------------
#define K1_AH 0
#define K1_AL 16384
#define K1_BT 32768
#define K1_BS 40960
#define K1_SMEM 41216

__global__ __launch_bounds__(256) void k1_proj(
    const float* __restrict__ x, const float* __restrict__ bq)
{
    extern __shared__ char smc[];
    const uint32_t sb = smem_u32(smc);
    float* bs = (float*)(smc + K1_BS);
    const int tid = threadIdx.x, lane = tid & 31, w = tid >> 5;
    const int r0 = blockIdx.x * 128;
    const int b = r0 >> 11;
    const int t0l = r0 & (TT - 1);

    if (tid < 64) bs[tid] = bq[tid];

    const int arow = lane & 15;
    const int acol = (lane & 16) >> 1;
    const int brow = (lane & 7) | ((lane & 16) >> 1);
    const int bcol = lane & 8;

    float acc[8][4];
    #pragma unroll
    for (int t = 0; t < 8; t++)
        #pragma unroll
        for (int e = 0; e < 4; e++) acc[t][e] = 0.f;

    for (int kc = 0; kc < 8; kc++) {
        __syncthreads();
        // ---- x chunk [128 rows][64 k] fp32 -> fp16 hi/lo swizzled tiles ----
        #pragma unroll
        for (int it = 0; it < 4; it++) {
            int idx = it*256 + tid;
            int r = idx >> 3, kg = idx & 7;
            const float* xp = x + (size_t)(r0 + r)*EE + kc*64 + kg*8;
            float4 v0 = *(const float4*)(xp);
            float4 v1 = *(const float4*)(xp + 4);
            float vv[8] = {v0.x,v0.y,v0.z,v0.w,v1.x,v1.y,v1.z,v1.w};
            uint32_t h[8], l[8];
            #pragma unroll
            for (int q2 = 0; q2 < 8; q2++) {
                __half hh = __float2half_rn(vv[q2]);
                h[q2] = (uint32_t)__half_as_ushort(hh);
                l[q2] = (uint32_t)__half_as_ushort(__float2half_rn(vv[q2] - __half2float(hh)));
            }
            uint4 uh, ul;
            uh.x = h[0]|(h[1]<<16); uh.y = h[2]|(h[3]<<16);
            uh.z = h[4]|(h[5]<<16); uh.w = h[6]|(h[7]<<16);
            ul.x = l[0]|(l[1]<<16); ul.y = l[2]|(l[3]<<16);
            ul.z = l[4]|(l[5]<<16); ul.w = l[6]|(l[7]<<16);
            *(uint4*)(smc + K1_AH + SWZ(r*128 + kg*16)) = uh;
            *(uint4*)(smc + K1_AL + SWZ(r*128 + kg*16)) = ul;
        }
        // ---- W tile: coalesced fp16 load from g_wt [64 d][512 k] ----
        #pragma unroll
        for (int it = 0; it < 2; it++) {
            int idx = it*256 + tid;
            int d = idx >> 3, kg = idx & 7;
            uint4 uh = *(const uint4*)(g_wt + (size_t)d*EE + kc*64 + kg*8);
            *(uint4*)(smc + K1_BT + SWZ(d*128 + kg*16)) = uh;
        }
        __syncthreads();
        #pragma unroll
        for (int ks = 0; ks < 4; ks++) {
            uint32_t ah[4], al[4], bbw[4][4];
            LDSM4(ah[0], ah[1], ah[2], ah[3],
                  sb + K1_AH + SWZ((w*16 + arow)*128 + (ks*16 + acol)*2));
            LDSM4(al[0], al[1], al[2], al[3],
                  sb + K1_AL + SWZ((w*16 + arow)*128 + (ks*16 + acol)*2));
            #pragma unroll
            for (int ng = 0; ng < 4; ng++)
                LDSM4(bbw[ng][0], bbw[ng][1], bbw[ng][2], bbw[ng][3],
                      sb + K1_BT + SWZ((ng*16 + brow)*128 + (ks*16 + bcol)*2));
            #pragma unroll
            for (int nt = 0; nt < 8; nt++)
                mma_f16(acc[nt], ah, bbw[nt>>1][(nt&1)*2], bbw[nt>>1][(nt&1)*2+1]);
            #pragma unroll
            for (int nt = 0; nt < 8; nt++)
                mma_f16(acc[nt], al, bbw[nt>>1][(nt&1)*2], bbw[nt>>1][(nt&1)*2+1]);
        }
    }
    __syncthreads();

    uint16_t* st = (uint16_t*)smc;   // [64 d][132 rows]
    const int g = lane >> 2;
    const int c2 = (lane & 3) * 2;
    #pragma unroll
    for (int nt = 0; nt < 8; nt++) {
        int col = nt*8 + c2;
        float b0 = bs[col], b1 = bs[col+1];
        uint32_t h00 = (uint32_t)__half_as_ushort(__float2half_rn(acc[nt][0] + b0));
        uint32_t h01 = (uint32_t)__half_as_ushort(__float2half_rn(acc[nt][1] + b1));
        uint32_t h10 = (uint32_t)__half_as_ushort(__float2half_rn(acc[nt][2] + b0));
        uint32_t h11 = (uint32_t)__half_as_ushort(__float2half_rn(acc[nt][3] + b1));
        int row = w*16 + g;
        *(uint32_t*)(g_qh + (size_t)(r0 + row)*DD + col)     = h00 | (h01 << 16);
        *(uint32_t*)(g_qh + (size_t)(r0 + row + 8)*DD + col) = h10 | (h11 << 16);
        st[col*132 + row]         = (uint16_t)h00;
        st[(col+1)*132 + row]     = (uint16_t)h01;
        st[col*132 + row + 8]     = (uint16_t)h10;
        st[(col+1)*132 + row + 8] = (uint16_t)h11;
    }
    __syncthreads();
    #pragma unroll
    for (int it = 0; it < 4; it++) {
        int idx = it*256 + tid;
        int d = idx >> 4, tg = idx & 15;
        uint32_t u[8];
        #pragma unroll
        for (int t2 = 0; t2 < 8; t2++) u[t2] = (uint32_t)st[d*132 + tg*8 + t2];
        uint4 o;
        o.x = u[0]|(u[1]<<16); o.y = u[2]|(u[3]<<16);
        o.z = u[4]|(u[5]<<16); o.w = u[6]|(u[7]<<16);
        *(uint4*)(g_qTh + ((size_t)b*DD + d)*TT + t0l + tg*8) = o;
    }
}

// ---------------------------------------------------------------------------
// KA: stats. S̃ = qh_i . qh_j^T (consistent with KB); exp2 partial sums.
// mt-outer loop interleaves MUFU(mt) with MMA(mt+1). grid (136, 16).
// ---------------------------------------------------------------------------
#define KA_SMEM (32768 + 2048 + 1024)

__global__ __launch_bounds__(256) void ka_stats()
{
    extern __shared__ char smc[];
    float* rowpart = (float*)(smc + 32768);
    float* colpart = (float*)(smc + 32768 + 2048);
    const uint32_t sb = smem_u32(smc);
    const int tid = threadIdx.x, lane = tid & 31, w = tid >> 5;
    const int b = blockIdx.y;
    int jy = 0, rem = blockIdx.x;
    while (rem >= 16 - jy) { rem -= 16 - jy; jy++; }
    const int ix = jy + rem;
    const int i0 = ix * 128, j0 = jy * 128;

    #pragma unroll
    for (int it = 0; it < 8; it++) {
        int idx = it*256 + tid;
        int tile = idx >> 10;
        int r = (idx >> 3) & 127, ch = idx & 7;
        int grow = (tile == 0) ? (i0 + r) : (j0 + r);
        uint4 v = *(const uint4*)(g_qh + ((size_t)(b*TT + grow))*DD + ch*8);
        *(uint4*)(smc + tile*16384 + SWZ(r*128 + ch*16)) = v;
    }
    __syncthreads();

    const int wm = w >> 2, wn = w & 3;
    const int arow = lane & 15;
    const int acol = (lane & 16) >> 1;
    const int brow = (lane & 7) | ((lane & 16) >> 1);
    const int bcol = lane & 8;
    const int r_i = lane >> 2;
    const bool diag = (ix == jy);

    // preload all B fragments (4 ks x 2 ng)
    uint32_t bb[4][2][4];
    #pragma unroll
    for (int ks = 0; ks < 4; ks++)
        #pragma unroll
        for (int ng = 0; ng < 2; ng++)
            LDSM4(bb[ks][ng][0], bb[ks][ng][1], bb[ks][ng][2], bb[ks][ng][3],
                  sb + 16384 + SWZ((wn*32 + ng*16 + brow)*128 + (ks*16 + bcol)*2));

    float rp[4][2], cp[4][2];
    #pragma unroll
    for (int t = 0; t < 4; t++) { rp[t][0]=rp[t][1]=0.f; cp[t][0]=cp[t][1]=0.f; }

    #pragma unroll
    for (int mt = 0; mt < 4; mt++) {
        float d[4][4];
        #pragma unroll
        for (int t = 0; t < 4; t++)
            #pragma unroll
            for (int e = 0; e < 4; e++) d[t][e] = 0.f;
        #pragma unroll
        for (int ks = 0; ks < 4; ks++) {
            uint32_t a[4];
            LDSM4(a[0], a[1], a[2], a[3],
                  sb + SWZ((wm*64 + mt*16 + arow)*128 + (ks*16 + acol)*2));
            #pragma unroll
            for (int nt = 0; nt < 4; nt++)
                mma_f16(d[nt], a, bb[ks][nt>>1][(nt&1)*2], bb[ks][nt>>1][(nt&1)*2+1]);
        }
        // exp2 partials for this mt (overlaps next mt's MMAs)
        #pragma unroll
        for (int nt = 0; nt < 4; nt++) {
            float e0 = exp2f(d[nt][0]*LOG2E8);
            float e1 = exp2f(d[nt][1]*LOG2E8);
            float e2 = exp2f(d[nt][2]*LOG2E8);
            float e3 = exp2f(d[nt][3]*LOG2E8);
            rp[mt][0] += e0 + e1;  rp[mt][1] += e2 + e3;
            cp[nt][0] += e0 + e2;  cp[nt][1] += e1 + e3;
        }
    }

    #pragma unroll
    for (int mt = 0; mt < 4; mt++) {
        float r0 = rp[mt][0], r1 = rp[mt][1];
        r0 += __shfl_xor_sync(0xffffffffu, r0, 1); r0 += __shfl_xor_sync(0xffffffffu, r0, 2);
        r1 += __shfl_xor_sync(0xffffffffu, r1, 1); r1 += __shfl_xor_sync(0xffffffffu, r1, 2);
        if ((lane & 3) == 0) {
            int rl = wm*64 + mt*16 + r_i;
            rowpart[wn*128 + rl]     = r0;
            rowpart[wn*128 + rl + 8] = r1;
        }
    }
    #pragma unroll
    for (int nt = 0; nt < 4; nt++) {
        float c0 = cp[nt][0], c1 = cp[nt][1];
        c0 += __shfl_xor_sync(0xffffffffu, c0, 4); c0 += __shfl_xor_sync(0xffffffffu, c0, 8);
        c0 += __shfl_xor_sync(0xffffffffu, c0, 16);
        c1 += __shfl_xor_sync(0xffffffffu, c1, 4); c1 += __shfl_xor_sync(0xffffffffu, c1, 8);
        c1 += __shfl_xor_sync(0xffffffffu, c1, 16);
        if (lane < 4) {
            int cl = wn*32 + nt*8 + lane*2;
            colpart[wm*128 + cl]     = c0;
            colpart[wm*128 + cl + 1] = c1;
        }
    }
    __syncthreads();

    if (tid < 128) {
        float rs = rowpart[tid] + rowpart[128+tid] + rowpart[256+tid] + rowpart[384+tid];
        g_part[((size_t)(b*TT + i0 + tid))*16 + jy] = rs;
        if (!diag) {
            float cs = colpart[tid] + colpart[128+tid];
            g_part[((size_t)(b*TT + j0 + tid))*16 + ix] = cs;
        }
    }
}

// ---------------------------------------------------------------------------
// K3': c2[n] = log2( sum of 16 partials )
// ---------------------------------------------------------------------------
__global__ __launch_bounds__(256) void k3_logz()
{
    const int n = blockIdx.x * 256 + threadIdx.x;
    const float* p = g_part + (size_t)n * 16;
    float4 a = *(const float4*)(p);
    float4 b = *(const float4*)(p + 4);
    float4 c = *(const float4*)(p + 8);
    float4 e = *(const float4*)(p + 12);
    float s = a.x + a.y + a.z + a.w;
    s += b.x + b.y + b.z + b.w;
    s += c.x + c.y + c.z + c.w;
    s += e.x + e.y + e.z + e.w;
    g_c[n] = log2f(s);
}

// ---------------------------------------------------------------------------
// KB: fused out = P.q; S̃ recomputed (consistent with KA), P fp16 via exp2.
// i-tile 256, 8 warps x m32, q_i A-fragments cached in registers.
// grid (8 i-tiles, 16 b) = 128 CTAs, 256 threads, 1 CTA/SM.
// ---------------------------------------------------------------------------
#define KB_STRIDE 16640
#define QJH(buf) ((buf)*KB_STRIDE)
#define QTH(buf) ((buf)*KB_STRIDE + 8192)
#define CBUF(buf) ((buf)*KB_STRIDE + 16384)
#define QI_H (2*KB_STRIDE)
#define KB_SMEM (2*KB_STRIDE + 32768)

__global__ __launch_bounds__(256, 1) void kb_fused(float* __restrict__ out)
{
    extern __shared__ char smc[];
    const uint32_t sb = smem_u32(smc);
    const int tid = threadIdx.x, lane = tid & 31, w = tid >> 5;
    const int i0 = blockIdx.x * 256, b = blockIdx.y;

    const uint16_t* qh  = g_qh  + (size_t)b * TT * DD;
    const uint16_t* qTh = g_qTh + (size_t)b * DD * TT;
    const float*    cb  = g_c + b * TT;

    #pragma unroll
    for (int it = 0; it < 8; it++) {
        int idx = it*256 + tid;
        int r = idx >> 3, seg = idx & 7;
        *(uint4*)(smc + QI_H + SWZ(r*128 + seg*16)) =
            *(const uint4*)(qh + (size_t)(i0 + r)*DD + seg*8);
    }

    auto prefetch = [&](int c, int buf) {
        const int j0c = c * 64;
        #pragma unroll
        for (int k2 = 0; k2 < 2; k2++) {
            int idx = k2*256 + tid;
            int r = idx >> 3, seg = idx & 7;
            CPA16(sb + QJH(buf) + SWZ(r*128 + seg*16),
                  (const void*)(qh + (size_t)(j0c + r)*DD + seg*8));
            CPA16(sb + QTH(buf) + SWZ(r*128 + seg*16),
                  (const void*)(qTh + (size_t)r*TT + j0c + seg*8));
        }
        if (tid < 16)
            CPA16(sb + CBUF(buf) + tid*16, (const void*)(cb + j0c + tid*4));
    };

    prefetch(0, 0); CP_COMMIT();
    prefetch(1, 1); CP_COMMIT();
    __syncthreads();

    const int arow = lane & 15;
    const int acol = (lane & 16) >> 1;
    const int brow = (lane & 7) | ((lane & 16) >> 1);
    const int bcol = lane & 8;

    uint32_t aq[2][4][4];
    #pragma unroll
    for (int mt = 0; mt < 2; mt++)
        #pragma unroll
        for (int ks = 0; ks < 4; ks++)
            LDSM4(aq[mt][ks][0], aq[mt][ks][1], aq[mt][ks][2], aq[mt][ks][3],
                  sb + QI_H + SWZ((w*32 + mt*16 + arow)*128 + (ks*16 + acol)*2));

    float o[2][8][4];
    #pragma unroll
    for (int mt = 0; mt < 2; mt++)
        #pragma unroll
        for (int t = 0; t < 8; t++)
            #pragma unroll
            for (int e = 0; e < 4; e++) o[mt][t][e] = 0.f;

    for (int c = 0; c < 32; c++) {
        const int buf = c & 1;
        CP_WAIT1();
        __syncthreads();

        #pragma unroll
        for (int half = 0; half < 2; half++) {
            float s[2][4][4];
            #pragma unroll
            for (int mt = 0; mt < 2; mt++)
                #pragma unroll
                for (int t = 0; t < 4; t++)
                    #pragma unroll
                    for (int e = 0; e < 4; e++) s[mt][t][e] = 0.f;

            #pragma unroll
            for (int ks = 0; ks < 4; ks++) {
                uint32_t bb[2][4];
                #pragma unroll
                for (int ng = 0; ng < 2; ng++)
                    LDSM4(bb[ng][0], bb[ng][1], bb[ng][2], bb[ng][3],
                          sb + QJH(buf) + SWZ((half*32 + ng*16 + brow)*128 + (ks*16 + bcol)*2));
                #pragma unroll
                for (int mt = 0; mt < 2; mt++)
                    #pragma unroll
                    for (int nt = 0; nt < 4; nt++)
                        mma_f16(s[mt][nt], aq[mt][ks],
                                bb[nt>>1][(nt&1)*2], bb[nt>>1][(nt&1)*2+1]);
            }

            uint32_t ph01[2][4], ph23[2][4];
            #pragma unroll
            for (int mt = 0; mt < 2; mt++) {
                #pragma unroll
                for (int nt = 0; nt < 4; nt++) {
                    float2 cv = *(const float2*)(smc + CBUF(buf) + (half*32 + nt*8 + (lane&3)*2)*4);
                    float p0 = exp2f(fmaf(s[mt][nt][0], LOG2E8, -cv.x));
                    float p1 = exp2f(fmaf(s[mt][nt][1], LOG2E8, -cv.y));
                    float p2 = exp2f(fmaf(s[mt][nt][2], LOG2E8, -cv.x));
                    float p3 = exp2f(fmaf(s[mt][nt][3], LOG2E8, -cv.y));
                    uint16_t h0 = __half_as_ushort(__float2half_rn(p0));
                    uint16_t h1 = __half_as_ushort(__float2half_rn(p1));
                    uint16_t h2 = __half_as_ushort(__float2half_rn(p2));
                    uint16_t h3 = __half_as_ushort(__float2half_rn(p3));
                    ph01[mt][nt] = (uint32_t)h0 | ((uint32_t)h1 << 16);
                    ph23[mt][nt] = (uint32_t)h2 | ((uint32_t)h3 << 16);
                }
            }

            #pragma unroll
            for (int ks2 = 0; ks2 < 2; ks2++) {
                uint32_t bb[4][4];
                #pragma unroll
                for (int ng = 0; ng < 4; ng++)
                    LDSM4(bb[ng][0], bb[ng][1], bb[ng][2], bb[ng][3],
                          sb + QTH(buf) + SWZ((ng*16 + brow)*128 + (half*32 + ks2*16 + bcol)*2));
                #pragma unroll
                for (int mt = 0; mt < 2; mt++) {
                    uint32_t a2[4] = { ph01[mt][2*ks2], ph23[mt][2*ks2],
                                       ph01[mt][2*ks2+1], ph23[mt][2*ks2+1] };
                    #pragma unroll
                    for (int nt2 = 0; nt2 < 8; nt2++)
                        mma_f16(o[mt][nt2], a2,
                                bb[nt2>>1][(nt2&1)*2], bb[nt2>>1][(nt2&1)*2+1]);
                }
            }
        }

        __syncthreads();
        if (c + 2 < 32) prefetch(c + 2, buf);
        CP_COMMIT();
    }

    const int g = lane >> 2;
    const int t2 = (lane & 3) * 2;
    #pragma unroll
    for (int mt = 0; mt < 2; mt++) {
        #pragma unroll
        for (int nt2 = 0; nt2 < 8; nt2++) {
            int row = i0 + w*32 + mt*16 + g;
            int col = nt2*8 + t2;
            *(float2*)(out + ((size_t)b*TT + row)*DD + col) =
                make_float2(o[mt][nt2][0], o[mt][nt2][1]);
            *(float2*)(out + ((size_t)b*TT + row + 8)*DD + col) =
                make_float2(o[mt][nt2][2], o[mt][nt2][3]);
        }
    }
}

// ---------------------------------------------------------------------------
extern "C" void kernel_launch(void* const* d_in, const int* in_sizes, int n_in,
                              void* d_out, int out_size)
{
    const float* x  = (const float*)d_in[0];
    const float* Wq = (const float*)d_in[1];
    const float* bq = (const float*)d_in[2];
    float* out = (float*)d_out;

    cudaFuncSetAttribute(k1_proj,  cudaFuncAttributeMaxDynamicSharedMemorySize, K1_SMEM);
    cudaFuncSetAttribute(ka_stats, cudaFuncAttributeMaxDynamicSharedMemorySize, KA_SMEM);
    cudaFuncSetAttribute(kb_fused, cudaFuncAttributeMaxDynamicSharedMemorySize, KB_SMEM);

    k0_wcvt<<<EE/64, 256>>>(Wq);
    k1_proj<<<NN/128, 256, K1_SMEM>>>(x, bq);
    ka_stats<<<dim3(136, BB), 256, KA_SMEM>>>();
    k3_logz<<<NN/256, 256>>>();
    kb_fused<<<dim3(TT/256, BB), 256, KB_SMEM>>>(out);
}